// round 12
// baseline (speedup 1.0000x reference)
#include <cuda_runtime.h>
#include <cuda_bf16.h>
#include <cstdint>

#define B_    4
#define N_    1000
#define T_    12
#define D_    64
#define HID_  128
#define EF_   64
#define E_    64000
#define SEG_  (B_*N_)       // 4000
#define ROWS_ (SEG_*T_)     // 48000
#define TD_   (T_*D_)       // 768
#define TH_   (T_*HID_)     // 1536
#define MROWS_ (E_*T_)      // 768000
#define TILE_M 128
#define NTILE_ (MROWS_/TILE_M)   // 6000
#define SMAX_CAP 32

// ---------------- device scratch ----------------
__device__ float g_S1[ROWS_ * HID_];
__device__ float g_S2[ROWS_ * HID_];
__device__ int   g_cnt[2 * SEG_];
__device__ int   g_off[2 * (SEG_ + 1)];
__device__ int   g_cur[2 * SEG_];
__device__ int   g_csr_s[E_];
__device__ int   g_csr_r[E_];

// ---------------- mma.sync bf16 (sm_80+ legacy tensor path) ----------------
__device__ __forceinline__ void mma_bf16(float& d0, float& d1, float& d2, float& d3,
                                         uint32_t a0, uint32_t a1, uint32_t a2, uint32_t a3,
                                         uint32_t b0, uint32_t b1) {
    asm("mma.sync.aligned.m16n8k16.row.col.f32.bf16.bf16.f32 "
        "{%0,%1,%2,%3},{%4,%5,%6,%7},{%8,%9},{%0,%1,%2,%3};"
        : "+f"(d0), "+f"(d1), "+f"(d2), "+f"(d3)
        : "r"(a0), "r"(a1), "r"(a2), "r"(a3), "r"(b0), "r"(b1));
}

__device__ __forceinline__ void bf16_split2(float x, float y, uint32_t& hi, uint32_t& lo) {
    __nv_bfloat162 h2 = __float22bfloat162_rn(make_float2(x, y));
    hi = *(uint32_t*)&h2;
    float2 hf = __bfloat1622float2(h2);
    __nv_bfloat162 l2 = __float22bfloat162_rn(make_float2(x - hf.x, y - hf.y));
    lo = *(uint32_t*)&l2;
}

// ---------------- CSR build (parallel) ----------------
__global__ void k_zero() {
    int i = blockIdx.x * blockDim.x + threadIdx.x;
    if (i < 2 * SEG_) g_cnt[i] = 0;
}

__global__ void k_count(const int* __restrict__ bi, const int* __restrict__ si,
                        const int* __restrict__ ri) {
    int e = blockIdx.x * blockDim.x + threadIdx.x;
    if (e >= E_) return;
    int b = bi[e];
    atomicAdd(&g_cnt[b * N_ + si[e]], 1);
    atomicAdd(&g_cnt[SEG_ + b * N_ + ri[e]], 1);
}

__global__ void k_scan2() {
    int which = blockIdx.x;
    const int* cnt = g_cnt + which * SEG_;
    int* off = g_off + which * (SEG_ + 1);
    int* cur = g_cur + which * SEG_;
    __shared__ int part[1024];
    int tid = threadIdx.x;
    int l[4]; int s = 0;
#pragma unroll
    for (int j = 0; j < 4; j++) {
        int idx = tid * 4 + j;
        l[j] = (idx < SEG_) ? cnt[idx] : 0;
        s += l[j];
    }
    part[tid] = s;
    __syncthreads();
    for (int o = 1; o < 1024; o <<= 1) {
        int v = part[tid];
        int a = (tid >= o) ? part[tid - o] : 0;
        __syncthreads();
        part[tid] = v + a;
        __syncthreads();
    }
    int run = (tid > 0) ? part[tid - 1] : 0;
#pragma unroll
    for (int j = 0; j < 4; j++) {
        int idx = tid * 4 + j;
        if (idx < SEG_) { off[idx] = run; cur[idx] = run; run += l[j]; }
    }
    if (tid == 1023) off[SEG_] = part[1023];
}

__global__ void k_scatter(const int* __restrict__ bi, const int* __restrict__ si,
                          const int* __restrict__ ri) {
    int e = blockIdx.x * blockDim.x + threadIdx.x;
    if (e >= E_) return;
    int b = bi[e];
    int ps = atomicAdd(&g_cur[b * N_ + si[e]], 1);
    g_csr_s[ps] = e;
    int pr = atomicAdd(&g_cur[SEG_ + b * N_ + ri[e]], 1);
    g_csr_r[pr] = e;
}

// ---------------- node projection via mma (S1 = x@A1 + b12, S2 = x@A2) ----------------
#define NPM_B1H 0               // [4s][16nt][2reg][32] u32 = 16 KB
#define NPM_B1L 16384
#define NPM_B2H 32768
#define NPM_B2L 49152
#define NPM_BIAS 65536          // 128 floats
#define NPM_A   66048           // per warp 4 KB (hi 2 + lo 2), 8 warps
#define NPM_SMEM (NPM_A + 8*4096)   // 98,816 B

__global__ void __launch_bounds__(256)
k_nodeproj(const float* __restrict__ x,
           const float* __restrict__ A1w, const float* __restrict__ A1b,
           const float* __restrict__ A2w, const float* __restrict__ A2b) {
    extern __shared__ char smem[];
    int tid = threadIdx.x;
    int w = tid >> 5;
    int l = tid & 31;

    // layout word = ((s*16 + nt)*2 + reg)*32 + lane  ->  s = idx >> 10
    for (int idx = tid; idx < 4096; idx += 256) {
        int lane = idx & 31, reg = (idx >> 5) & 1, nt = (idx >> 6) & 15, s = idx >> 10;
        int k = s * 16 + reg * 8 + 2 * (lane & 3);
        int n = nt * 8 + (lane >> 2);
        uint32_t hi, lo;
        bf16_split2(A1w[k * 128 + n], A1w[(k + 1) * 128 + n], hi, lo);
        *(uint32_t*)(smem + NPM_B1H + idx * 4) = hi;
        *(uint32_t*)(smem + NPM_B1L + idx * 4) = lo;
        bf16_split2(A2w[k * 128 + n], A2w[(k + 1) * 128 + n], hi, lo);
        *(uint32_t*)(smem + NPM_B2H + idx * 4) = hi;
        *(uint32_t*)(smem + NPM_B2L + idx * 4) = lo;
    }
    if (tid < 128) *(float*)(smem + NPM_BIAS + tid * 4) = A1b[tid] + A2b[tid];
    __syncthreads();

    char* Ah = smem + NPM_A + w * 4096;
    char* Al = Ah + 2048;
    const float* biasSh = (const float*)(smem + NPM_BIAS);

    int rowBase = blockIdx.x * 128 + w * 16;
    {
        int s = l >> 3;
        int khi = (l >> 2) & 1;
        int lf_lo = l & 3;
#pragma unroll 4
        for (int j = 0; j < 16; j++) {
            float2 xv = *(const float2*)(x + (size_t)(rowBase + j) * 64 + 2 * l);
            uint32_t hi, lo;
            bf16_split2(xv.x, xv.y, hi, lo);
            int reg = (j >> 3) + 2 * khi;
            int lane_f = (j & 7) * 4 + lf_lo;
            uint32_t word = (uint32_t)((s * 4 + reg) * 32 + (lane_f ^ (4 * s)));
            *(uint32_t*)(Ah + word * 4) = hi;
            *(uint32_t*)(Al + word * 4) = lo;
        }
    }
    __syncwarp();

    int lr0 = l >> 2;
    int col0 = 2 * (l & 3);

#pragma unroll
    for (int m = 0; m < 2; m++) {
        const char* BH = smem + (m == 0 ? NPM_B1H : NPM_B2H);
        const char* BL = smem + (m == 0 ? NPM_B1L : NPM_B2L);
        float acc[16][4];
#pragma unroll
        for (int nt = 0; nt < 16; nt++)
#pragma unroll
            for (int r = 0; r < 4; r++) acc[nt][r] = 0.f;
#pragma unroll
        for (int s = 0; s < 4; s++) {
            int lsw = l ^ (4 * s);
            uint32_t ah[4], al[4];
#pragma unroll
            for (int r = 0; r < 4; r++) {
                ah[r] = *(const uint32_t*)(Ah + ((s * 4 + r) * 32 + lsw) * 4);
                al[r] = *(const uint32_t*)(Al + ((s * 4 + r) * 32 + lsw) * 4);
            }
#pragma unroll
            for (int nt = 0; nt < 16; nt++) {
                uint32_t boff = (uint32_t)((((s * 16 + nt) * 2) * 32 + l) * 4);
                uint32_t bh0 = *(const uint32_t*)(BH + boff);
                uint32_t bh1 = *(const uint32_t*)(BH + boff + 128);
                uint32_t bl0 = *(const uint32_t*)(BL + boff);
                uint32_t bl1 = *(const uint32_t*)(BL + boff + 128);
                mma_bf16(acc[nt][0], acc[nt][1], acc[nt][2], acc[nt][3],
                         ah[0], ah[1], ah[2], ah[3], bh0, bh1);
                mma_bf16(acc[nt][0], acc[nt][1], acc[nt][2], acc[nt][3],
                         al[0], al[1], al[2], al[3], bh0, bh1);
                mma_bf16(acc[nt][0], acc[nt][1], acc[nt][2], acc[nt][3],
                         ah[0], ah[1], ah[2], ah[3], bl0, bl1);
            }
        }
        float* out = (m == 0) ? g_S1 : g_S2;
        float* ob0 = out + (size_t)(rowBase + lr0) * 128;
        float* ob1 = out + (size_t)(rowBase + lr0 + 8) * 128;
#pragma unroll
        for (int nt = 0; nt < 16; nt++) {
            int c = nt * 8 + col0;
            float bz0 = (m == 0) ? biasSh[c] : 0.f;
            float bz1 = (m == 0) ? biasSh[c + 1] : 0.f;
            *(float2*)(ob0 + c) = make_float2(acc[nt][0] + bz0, acc[nt][1] + bz1);
            *(float2*)(ob1 + c) = make_float2(acc[nt][2] + bz0, acc[nt][3] + bz1);
        }
    }
}

// ---------------- tensor-core edge kernel: 4 warps x 32 rows, shared B loads ----------------
// Per-warp A smem: 2 sub-tiles x (hi 4 KB + lo 4 KB) = 16 KB. Block = 48 KB B + 64 KB A.
#define SM_B1H  0
#define SM_B1L  16384
#define SM_B2H  32768
#define SM_B2L  40960
#define SM_BIAS 49152
#define SM_A1   49408
#define EM_SMEM (SM_A1 + 4*16384)            // 114,944 B

__global__ void __launch_bounds__(128)
k_edge_mma(const int* __restrict__ bi, const int* __restrict__ si,
           const int* __restrict__ ri,
           const float* __restrict__ A3w, const float* __restrict__ A4w,
           const float* __restrict__ A4b, float* __restrict__ outv) {
    extern __shared__ char smem[];
    int tid = threadIdx.x;
    int w = tid >> 5;
    int l = tid & 31;

    for (int idx = tid; idx < 4096; idx += 128) {
        int lane = idx & 31, reg = (idx >> 5) & 1, nt = (idx >> 6) & 7, s = idx >> 9;
        int k = s * 16 + reg * 8 + 2 * (lane & 3);
        int n = nt * 8 + (lane >> 2);
        uint32_t hi, lo;
        bf16_split2(A3w[k * 64 + n], A3w[(k + 1) * 64 + n], hi, lo);
        *(uint32_t*)(smem + SM_B1H + idx * 4) = hi;
        *(uint32_t*)(smem + SM_B1L + idx * 4) = lo;
    }
    for (int idx = tid; idx < 2048; idx += 128) {
        int lane = idx & 31, reg = (idx >> 5) & 1, nt = (idx >> 6) & 7, s = idx >> 9;
        int k = s * 16 + reg * 8 + 2 * (lane & 3);
        int n = nt * 8 + (lane >> 2);
        uint32_t hi, lo;
        bf16_split2(A4w[k * 64 + n], A4w[(k + 1) * 64 + n], hi, lo);
        *(uint32_t*)(smem + SM_B2H + idx * 4) = hi;
        *(uint32_t*)(smem + SM_B2L + idx * 4) = lo;
    }
    if (tid < 64) *(float*)(smem + SM_BIAS + tid * 4) = A4b[tid];
    __syncthreads();

    char* Abase = smem + SM_A1 + w * 16384;   // [u][hi 4K | lo 4K]
    const float* biasSh = (const float*)(smem + SM_BIAS);

    int bs   = l >> 2;
    int bkhi = (l >> 1) & 1;
    int blpar= l & 1;
    int lr0 = l >> 2;
    int col0 = 2 * (l & 3);

    for (int tile = blockIdx.x; tile < NTILE_; tile += gridDim.x) {
        __syncwarp();
        // ---- build 32 rows: gather + relu-diff -> swizzled A1 fragments (2 sub-tiles) ----
#pragma unroll
        for (int u = 0; u < 2; u++) {
            char* Ah = Abase + u * 8192;
            char* Al = Ah + 4096;
#pragma unroll 2
            for (int j = 0; j < 16; j++) {
                int g = tile * TILE_M + w * 32 + u * 16 + j;
                int e = g / 12, tt = g - e * 12;
                int bb = bi[e];
                int ns = bb * N_ + si[e], nr = bb * N_ + ri[e];
                size_t o = (size_t)tt * 128 + 4 * l;
                float4 a  = *(const float4*)(g_S1 + (size_t)ns * TH_ + o);
                float4 d  = *(const float4*)(g_S2 + (size_t)ns * TH_ + o);
                float4 c  = *(const float4*)(g_S1 + (size_t)nr * TH_ + o);
                float4 b4 = *(const float4*)(g_S2 + (size_t)nr * TH_ + o);
                float h0 = fmaxf(a.x + b4.x, 0.f) - fmaxf(c.x + d.x, 0.f);
                float h1 = fmaxf(a.y + b4.y, 0.f) - fmaxf(c.y + d.y, 0.f);
                float h2 = fmaxf(a.z + b4.z, 0.f) - fmaxf(c.z + d.z, 0.f);
                float h3 = fmaxf(a.w + b4.w, 0.f) - fmaxf(c.w + d.w, 0.f);
                uint32_t hiA, loA, hiB, loB;
                bf16_split2(h0, h1, hiA, loA);
                bf16_split2(h2, h3, hiB, loB);
                int reg = (j >> 3) + 2 * bkhi;
                int lf0 = (j & 7) * 4 + 2 * blpar;
                uint32_t word = (uint32_t)((bs * 4 + reg) * 32 + (lf0 ^ (4 * bs)));
                *(uint2*)(Ah + word * 4) = make_uint2(hiA, hiB);
                *(uint2*)(Al + word * 4) = make_uint2(loA, loB);
            }
        }
        __syncwarp();

        // ---- GEMM1: 2 sub-tiles share every B-fragment load ----
        float acc[2][8][4];
#pragma unroll
        for (int u = 0; u < 2; u++)
#pragma unroll
            for (int nt = 0; nt < 8; nt++)
#pragma unroll
                for (int r = 0; r < 4; r++) acc[u][nt][r] = 0.f;
#pragma unroll
        for (int s = 0; s < 8; s++) {
            int lsw = l ^ (4 * s);
            uint32_t ah[2][4], al[2][4];
#pragma unroll
            for (int u = 0; u < 2; u++)
#pragma unroll
                for (int r = 0; r < 4; r++) {
                    ah[u][r] = *(const uint32_t*)(Abase + u * 8192 + ((s * 4 + r) * 32 + lsw) * 4);
                    al[u][r] = *(const uint32_t*)(Abase + u * 8192 + 4096 + ((s * 4 + r) * 32 + lsw) * 4);
                }
#pragma unroll
            for (int nt = 0; nt < 8; nt++) {
                uint32_t boff = (uint32_t)((((s * 8 + nt) * 2) * 32 + l) * 4);
                uint32_t bh0 = *(const uint32_t*)(smem + SM_B1H + boff);
                uint32_t bh1 = *(const uint32_t*)(smem + SM_B1H + boff + 128);
                uint32_t bl0 = *(const uint32_t*)(smem + SM_B1L + boff);
                uint32_t bl1 = *(const uint32_t*)(smem + SM_B1L + boff + 128);
#pragma unroll
                for (int u = 0; u < 2; u++) {
                    mma_bf16(acc[u][nt][0], acc[u][nt][1], acc[u][nt][2], acc[u][nt][3],
                             ah[u][0], ah[u][1], ah[u][2], ah[u][3], bh0, bh1);
                    mma_bf16(acc[u][nt][0], acc[u][nt][1], acc[u][nt][2], acc[u][nt][3],
                             al[u][0], al[u][1], al[u][2], al[u][3], bh0, bh1);
                    mma_bf16(acc[u][nt][0], acc[u][nt][1], acc[u][nt][2], acc[u][nt][3],
                             ah[u][0], ah[u][1], ah[u][2], ah[u][3], bl0, bl1);
                }
            }
        }
        __syncwarp();

        // ---- epilogue1: relu + split -> A2 fragments (overlay A1 slots per sub-tile) ----
#pragma unroll
        for (int u = 0; u < 2; u++) {
            char* A2h = Abase + u * 8192;
            char* A2l = A2h + 4096;
#pragma unroll
            for (int nt = 0; nt < 8; nt++) {
                float x0 = fmaxf(acc[u][nt][0], 0.f), x1 = fmaxf(acc[u][nt][1], 0.f);
                float x2 = fmaxf(acc[u][nt][2], 0.f), x3 = fmaxf(acc[u][nt][3], 0.f);
                uint32_t hi0, lo0, hi1, lo1;
                bf16_split2(x0, x1, hi0, lo0);
                bf16_split2(x2, x3, hi1, lo1);
                int s2 = nt >> 1, khi = nt & 1;
                int lsw = l ^ (4 * s2);
                uint32_t o0 = (uint32_t)(((s2 * 4 + 2 * khi + 0) * 32 + lsw) * 4);
                uint32_t o1 = (uint32_t)(((s2 * 4 + 2 * khi + 1) * 32 + lsw) * 4);
                *(uint32_t*)(A2h + o0) = hi0;
                *(uint32_t*)(A2h + o1) = hi1;
                *(uint32_t*)(A2l + o0) = lo0;
                *(uint32_t*)(A2l + o1) = lo1;
            }
        }
        __syncwarp();

        // ---- GEMM2: shared B loads across sub-tiles ----
        float vac[2][8][4];
#pragma unroll
        for (int u = 0; u < 2; u++)
#pragma unroll
            for (int nt = 0; nt < 8; nt++)
#pragma unroll
                for (int r = 0; r < 4; r++) vac[u][nt][r] = 0.f;
#pragma unroll
        for (int s = 0; s < 4; s++) {
            int lsw = l ^ (4 * s);
            uint32_t ah[2][4], al[2][4];
#pragma unroll
            for (int u = 0; u < 2; u++)
#pragma unroll
                for (int r = 0; r < 4; r++) {
                    ah[u][r] = *(const uint32_t*)(Abase + u * 8192 + ((s * 4 + r) * 32 + lsw) * 4);
                    al[u][r] = *(const uint32_t*)(Abase + u * 8192 + 4096 + ((s * 4 + r) * 32 + lsw) * 4);
                }
#pragma unroll
            for (int nt = 0; nt < 8; nt++) {
                uint32_t boff = (uint32_t)((((s * 8 + nt) * 2) * 32 + l) * 4);
                uint32_t bh0 = *(const uint32_t*)(smem + SM_B2H + boff);
                uint32_t bh1 = *(const uint32_t*)(smem + SM_B2H + boff + 128);
                uint32_t bl0 = *(const uint32_t*)(smem + SM_B2L + boff);
                uint32_t bl1 = *(const uint32_t*)(smem + SM_B2L + boff + 128);
#pragma unroll
                for (int u = 0; u < 2; u++) {
                    mma_bf16(vac[u][nt][0], vac[u][nt][1], vac[u][nt][2], vac[u][nt][3],
                             ah[u][0], ah[u][1], ah[u][2], ah[u][3], bh0, bh1);
                    mma_bf16(vac[u][nt][0], vac[u][nt][1], vac[u][nt][2], vac[u][nt][3],
                             al[u][0], al[u][1], al[u][2], al[u][3], bh0, bh1);
                    mma_bf16(vac[u][nt][0], vac[u][nt][1], vac[u][nt][2], vac[u][nt][3],
                             ah[u][0], ah[u][1], ah[u][2], ah[u][3], bl0, bl1);
                }
            }
        }

        // ---- epilogue2: bias + STG, both sub-tiles ----
#pragma unroll
        for (int u = 0; u < 2; u++) {
            int g0 = tile * TILE_M + w * 32 + u * 16 + lr0;
            int e0 = g0 / 12, t0 = g0 - 12 * e0;
            int g1 = g0 + 8;
            int e1 = g1 / 12, t1 = g1 - 12 * e1;
            float* ob0 = outv + (size_t)e0 * TD_ + t0 * 64;
            float* ob1 = outv + (size_t)e1 * TD_ + t1 * 64;
#pragma unroll
            for (int nt = 0; nt < 8; nt++) {
                int c = nt * 8 + col0;
                float bz0 = biasSh[c], bz1 = biasSh[c + 1];
                *(float2*)(ob0 + c) = make_float2(vac[u][nt][0] + bz0, vac[u][nt][1] + bz1);
                *(float2*)(ob1 + c) = make_float2(vac[u][nt][2] + bz0, vac[u][nt][3] + bz1);
            }
        }
    }
}

// ---------------- softmax: one block per segment, 256 thr, exp cached in dyn smem ----------------
#define SMAX_SMEM (SMAX_CAP * TD_ * 4)   // 98,304 B
__global__ void __launch_bounds__(256)
k_softmax(float* __restrict__ v) {
    extern __shared__ float buf[];
    int seg = blockIdx.x;
    int beg = g_off[seg], end = g_off[seg + 1];
    int n = end - beg;
    if (n <= 0) return;
    int tid = threadIdx.x;
    int c0 = tid, c1 = tid + 256, c2 = tid + 512;
    if (n <= SMAX_CAP) {
        float s0 = 0.f, s1 = 0.f, s2 = 0.f;
        for (int i = 0; i < n; i++) {
            const float* vp = v + (size_t)g_csr_s[beg + i] * TD_;
            float e0 = __expf(vp[c0]), e1 = __expf(vp[c1]), e2 = __expf(vp[c2]);
            buf[i * TD_ + c0] = e0; buf[i * TD_ + c1] = e1; buf[i * TD_ + c2] = e2;
            s0 += e0; s1 += e1; s2 += e2;
        }
        float r0 = 1.f / (s0 + 1e-12f), r1 = 1.f / (s1 + 1e-12f), r2 = 1.f / (s2 + 1e-12f);
        for (int i = 0; i < n; i++) {
            float* vp = v + (size_t)g_csr_s[beg + i] * TD_;
            vp[c0] = buf[i * TD_ + c0] * r0;
            vp[c1] = buf[i * TD_ + c1] * r1;
            vp[c2] = buf[i * TD_ + c2] * r2;
        }
    } else {
        float s0 = 0.f, s1 = 0.f, s2 = 0.f;
        for (int i = beg; i < end; i++) {
            const float* vp = v + (size_t)g_csr_s[i] * TD_;
            s0 += __expf(vp[c0]); s1 += __expf(vp[c1]); s2 += __expf(vp[c2]);
        }
        float r0 = 1.f / (s0 + 1e-12f), r1 = 1.f / (s1 + 1e-12f), r2 = 1.f / (s2 + 1e-12f);
        for (int i = beg; i < end; i++) {
            float* vp = v + (size_t)g_csr_s[i] * TD_;
            vp[c0] = __expf(vp[c0]) * r0;
            vp[c1] = __expf(vp[c1]) * r1;
            vp[c2] = __expf(vp[c2]) * r2;
        }
    }
}

// ---------------- per-receiver aggregation + x update ----------------
__global__ void k_aggregate(const float* __restrict__ x, const float* __restrict__ v,
                            const int* __restrict__ bi, const int* __restrict__ si,
                            float* __restrict__ outx) {
    int seg = blockIdx.x;
    int tid = threadIdx.x;
    int beg = g_off[(SEG_ + 1) + seg], end = g_off[(SEG_ + 1) + seg + 1];
    int c0 = tid, c1 = tid + 256, c2 = tid + 512;
    float a0 = 0.f, a1 = 0.f, a2 = 0.f;
#pragma unroll 2
    for (int i = beg; i < end; i++) {
        int e = g_csr_r[i];
        int ns = bi[e] * N_ + si[e];
        const float* vp = v + (size_t)e * TD_;
        const float* xs = x + (size_t)ns * TD_;
        a0 = fmaf(vp[c0], xs[c0], a0);
        a1 = fmaf(vp[c1], xs[c1], a1);
        a2 = fmaf(vp[c2], xs[c2], a2);
    }
    const float* xr = x + (size_t)seg * TD_;
    float* o = outx + (size_t)seg * TD_;
    o[c0] = xr[c0] + 0.1f * (a0 - xr[c0]);
    o[c1] = xr[c1] + 0.1f * (a1 - xr[c1]);
    o[c2] = xr[c2] + 0.1f * (a2 - xr[c2]);
}

// ---------------- launch ----------------
extern "C" void kernel_launch(void* const* d_in, const int* in_sizes, int n_in,
                              void* d_out, int out_size) {
    const float* x   = (const float*)d_in[0];
    const int*   bi  = (const int*)d_in[1];
    const int*   si  = (const int*)d_in[2];
    const int*   ri  = (const int*)d_in[3];
    const float* A1w = (const float*)d_in[4];
    const float* A1b = (const float*)d_in[5];
    const float* A2w = (const float*)d_in[6];
    const float* A2b = (const float*)d_in[7];
    const float* A3w = (const float*)d_in[8];
    // d_in[9] = A3_b: cancels in z_ij - z_ji
    const float* A4w = (const float*)d_in[10];
    const float* A4b = (const float*)d_in[11];

    float* outx = (float*)d_out;
    float* outv = outx + (size_t)ROWS_ * D_;

    cudaFuncSetAttribute(k_nodeproj, cudaFuncAttributeMaxDynamicSharedMemorySize, NPM_SMEM);
    cudaFuncSetAttribute(k_edge_mma, cudaFuncAttributeMaxDynamicSharedMemorySize, EM_SMEM);
    cudaFuncSetAttribute(k_softmax,  cudaFuncAttributeMaxDynamicSharedMemorySize, SMAX_SMEM);

    // edge has no CSR dependency -> placed at kernel-launch index 3 for ncu capture
    k_zero<<<32, 256>>>();                                            // 0
    k_count<<<(E_ + 255) / 256, 256>>>(bi, si, ri);                   // 1
    k_nodeproj<<<ROWS_ / 128, 256, NPM_SMEM>>>(x, A1w, A1b, A2w, A2b);// 2
    k_edge_mma<<<296, 128, EM_SMEM>>>(bi, si, ri, A3w, A4w, A4b, outv);// 3 (profiled)
    k_scan2<<<2, 1024>>>();                                           // 4
    k_scatter<<<(E_ + 255) / 256, 256>>>(bi, si, ri);                 // 5
    k_softmax<<<SEG_, 256, SMAX_SMEM>>>(outv);                        // 6
    k_aggregate<<<SEG_, 256>>>(x, outv, bi, si, outx);                // 7
}

// round 13
// speedup vs baseline: 1.0519x; 1.0519x over previous
#include <cuda_runtime.h>
#include <cuda_bf16.h>
#include <cstdint>

#define B_    4
#define N_    1000
#define T_    12
#define D_    64
#define HID_  128
#define EF_   64
#define E_    64000
#define SEG_  (B_*N_)       // 4000
#define ROWS_ (SEG_*T_)     // 48000
#define TD_   (T_*D_)       // 768
#define TD4_  (TD_/4)       // 192
#define TH_   (T_*HID_)     // 1536
#define MROWS_ (E_*T_)      // 768000
#define TILE_M 128
#define NTILE_ (MROWS_/TILE_M)   // 6000
#define SMAX_CAP 32

// ---------------- device scratch ----------------
__device__ float g_S1[ROWS_ * HID_];
__device__ float g_S2[ROWS_ * HID_];
__device__ int   g_cnt[2 * SEG_];
__device__ int   g_off[2 * (SEG_ + 1)];
__device__ int   g_cur[2 * SEG_];
__device__ int   g_csr_s[E_];
__device__ int   g_csr_r[E_];

// ---------------- mma.sync bf16 (sm_80+ legacy tensor path) ----------------
__device__ __forceinline__ void mma_bf16(float& d0, float& d1, float& d2, float& d3,
                                         uint32_t a0, uint32_t a1, uint32_t a2, uint32_t a3,
                                         uint32_t b0, uint32_t b1) {
    asm("mma.sync.aligned.m16n8k16.row.col.f32.bf16.bf16.f32 "
        "{%0,%1,%2,%3},{%4,%5,%6,%7},{%8,%9},{%0,%1,%2,%3};"
        : "+f"(d0), "+f"(d1), "+f"(d2), "+f"(d3)
        : "r"(a0), "r"(a1), "r"(a2), "r"(a3), "r"(b0), "r"(b1));
}

__device__ __forceinline__ void bf16_split2(float x, float y, uint32_t& hi, uint32_t& lo) {
    __nv_bfloat162 h2 = __float22bfloat162_rn(make_float2(x, y));
    hi = *(uint32_t*)&h2;
    float2 hf = __bfloat1622float2(h2);
    __nv_bfloat162 l2 = __float22bfloat162_rn(make_float2(x - hf.x, y - hf.y));
    lo = *(uint32_t*)&l2;
}

// ---------------- CSR build (parallel) ----------------
__global__ void k_zero() {
    int i = blockIdx.x * blockDim.x + threadIdx.x;
    if (i < 2 * SEG_) g_cnt[i] = 0;
}

__global__ void k_count(const int* __restrict__ bi, const int* __restrict__ si,
                        const int* __restrict__ ri) {
    int e = blockIdx.x * blockDim.x + threadIdx.x;
    if (e >= E_) return;
    int b = bi[e];
    atomicAdd(&g_cnt[b * N_ + si[e]], 1);
    atomicAdd(&g_cnt[SEG_ + b * N_ + ri[e]], 1);
}

__global__ void k_scan2() {
    int which = blockIdx.x;
    const int* cnt = g_cnt + which * SEG_;
    int* off = g_off + which * (SEG_ + 1);
    int* cur = g_cur + which * SEG_;
    __shared__ int part[1024];
    int tid = threadIdx.x;
    int l[4]; int s = 0;
#pragma unroll
    for (int j = 0; j < 4; j++) {
        int idx = tid * 4 + j;
        l[j] = (idx < SEG_) ? cnt[idx] : 0;
        s += l[j];
    }
    part[tid] = s;
    __syncthreads();
    for (int o = 1; o < 1024; o <<= 1) {
        int v = part[tid];
        int a = (tid >= o) ? part[tid - o] : 0;
        __syncthreads();
        part[tid] = v + a;
        __syncthreads();
    }
    int run = (tid > 0) ? part[tid - 1] : 0;
#pragma unroll
    for (int j = 0; j < 4; j++) {
        int idx = tid * 4 + j;
        if (idx < SEG_) { off[idx] = run; cur[idx] = run; run += l[j]; }
    }
    if (tid == 1023) off[SEG_] = part[1023];
}

__global__ void k_scatter(const int* __restrict__ bi, const int* __restrict__ si,
                          const int* __restrict__ ri) {
    int e = blockIdx.x * blockDim.x + threadIdx.x;
    if (e >= E_) return;
    int b = bi[e];
    int ps = atomicAdd(&g_cur[b * N_ + si[e]], 1);
    g_csr_s[ps] = e;
    int pr = atomicAdd(&g_cur[SEG_ + b * N_ + ri[e]], 1);
    g_csr_r[pr] = e;
}

// ---------------- node projection via mma (S1 = x@A1 + b12, S2 = x@A2) ----------------
#define NPM_B1H 0               // [4s][16nt][2reg][32] u32 = 16 KB
#define NPM_B1L 16384
#define NPM_B2H 32768
#define NPM_B2L 49152
#define NPM_BIAS 65536          // 128 floats
#define NPM_A   66048           // per warp 4 KB (hi 2 + lo 2), 8 warps
#define NPM_SMEM (NPM_A + 8*4096)   // 98,816 B

__global__ void __launch_bounds__(256)
k_nodeproj(const float* __restrict__ x,
           const float* __restrict__ A1w, const float* __restrict__ A1b,
           const float* __restrict__ A2w, const float* __restrict__ A2b) {
    extern __shared__ char smem[];
    int tid = threadIdx.x;
    int w = tid >> 5;
    int l = tid & 31;

    // layout word = ((s*16 + nt)*2 + reg)*32 + lane  ->  s = idx >> 10
    for (int idx = tid; idx < 4096; idx += 256) {
        int lane = idx & 31, reg = (idx >> 5) & 1, nt = (idx >> 6) & 15, s = idx >> 10;
        int k = s * 16 + reg * 8 + 2 * (lane & 3);
        int n = nt * 8 + (lane >> 2);
        uint32_t hi, lo;
        bf16_split2(A1w[k * 128 + n], A1w[(k + 1) * 128 + n], hi, lo);
        *(uint32_t*)(smem + NPM_B1H + idx * 4) = hi;
        *(uint32_t*)(smem + NPM_B1L + idx * 4) = lo;
        bf16_split2(A2w[k * 128 + n], A2w[(k + 1) * 128 + n], hi, lo);
        *(uint32_t*)(smem + NPM_B2H + idx * 4) = hi;
        *(uint32_t*)(smem + NPM_B2L + idx * 4) = lo;
    }
    if (tid < 128) *(float*)(smem + NPM_BIAS + tid * 4) = A1b[tid] + A2b[tid];
    __syncthreads();

    char* Ah = smem + NPM_A + w * 4096;
    char* Al = Ah + 2048;
    const float* biasSh = (const float*)(smem + NPM_BIAS);

    int rowBase = blockIdx.x * 128 + w * 16;
    {
        int s = l >> 3;
        int khi = (l >> 2) & 1;
        int lf_lo = l & 3;
#pragma unroll 4
        for (int j = 0; j < 16; j++) {
            float2 xv = *(const float2*)(x + (size_t)(rowBase + j) * 64 + 2 * l);
            uint32_t hi, lo;
            bf16_split2(xv.x, xv.y, hi, lo);
            int reg = (j >> 3) + 2 * khi;
            int lane_f = (j & 7) * 4 + lf_lo;
            uint32_t word = (uint32_t)((s * 4 + reg) * 32 + (lane_f ^ (4 * s)));
            *(uint32_t*)(Ah + word * 4) = hi;
            *(uint32_t*)(Al + word * 4) = lo;
        }
    }
    __syncwarp();

    int lr0 = l >> 2;
    int col0 = 2 * (l & 3);

#pragma unroll
    for (int m = 0; m < 2; m++) {
        const char* BH = smem + (m == 0 ? NPM_B1H : NPM_B2H);
        const char* BL = smem + (m == 0 ? NPM_B1L : NPM_B2L);
        float acc[16][4];
#pragma unroll
        for (int nt = 0; nt < 16; nt++)
#pragma unroll
            for (int r = 0; r < 4; r++) acc[nt][r] = 0.f;
#pragma unroll
        for (int s = 0; s < 4; s++) {
            int lsw = l ^ (4 * s);
            uint32_t ah[4], al[4];
#pragma unroll
            for (int r = 0; r < 4; r++) {
                ah[r] = *(const uint32_t*)(Ah + ((s * 4 + r) * 32 + lsw) * 4);
                al[r] = *(const uint32_t*)(Al + ((s * 4 + r) * 32 + lsw) * 4);
            }
#pragma unroll
            for (int nt = 0; nt < 16; nt++) {
                uint32_t boff = (uint32_t)((((s * 16 + nt) * 2) * 32 + l) * 4);
                uint32_t bh0 = *(const uint32_t*)(BH + boff);
                uint32_t bh1 = *(const uint32_t*)(BH + boff + 128);
                uint32_t bl0 = *(const uint32_t*)(BL + boff);
                uint32_t bl1 = *(const uint32_t*)(BL + boff + 128);
                mma_bf16(acc[nt][0], acc[nt][1], acc[nt][2], acc[nt][3],
                         ah[0], ah[1], ah[2], ah[3], bh0, bh1);
                mma_bf16(acc[nt][0], acc[nt][1], acc[nt][2], acc[nt][3],
                         al[0], al[1], al[2], al[3], bh0, bh1);
                mma_bf16(acc[nt][0], acc[nt][1], acc[nt][2], acc[nt][3],
                         ah[0], ah[1], ah[2], ah[3], bl0, bl1);
            }
        }
        float* out = (m == 0) ? g_S1 : g_S2;
        float* ob0 = out + (size_t)(rowBase + lr0) * 128;
        float* ob1 = out + (size_t)(rowBase + lr0 + 8) * 128;
#pragma unroll
        for (int nt = 0; nt < 16; nt++) {
            int c = nt * 8 + col0;
            float bz0 = (m == 0) ? biasSh[c] : 0.f;
            float bz1 = (m == 0) ? biasSh[c + 1] : 0.f;
            *(float2*)(ob0 + c) = make_float2(acc[nt][0] + bz0, acc[nt][1] + bz1);
            *(float2*)(ob1 + c) = make_float2(acc[nt][2] + bz0, acc[nt][3] + bz1);
        }
    }
}

// ---------------- tensor-core edge kernel (R11 proven config: 8 warps x 16 rows) ----------------
#define SM_B1H  0
#define SM_B1L  16384
#define SM_B2H  32768
#define SM_B2L  40960
#define SM_BIAS 49152
#define SM_A1   49408
#define EM_SMEM (SM_A1 + 8*8192)             // 114,944 B

__global__ void __launch_bounds__(256)
k_edge_mma(const int* __restrict__ bi, const int* __restrict__ si,
           const int* __restrict__ ri,
           const float* __restrict__ A3w, const float* __restrict__ A4w,
           const float* __restrict__ A4b, float* __restrict__ outv) {
    extern __shared__ char smem[];
    int tid = threadIdx.x;
    int w = tid >> 5;
    int l = tid & 31;

    for (int idx = tid; idx < 4096; idx += 256) {
        int lane = idx & 31, reg = (idx >> 5) & 1, nt = (idx >> 6) & 7, s = idx >> 9;
        int k = s * 16 + reg * 8 + 2 * (lane & 3);
        int n = nt * 8 + (lane >> 2);
        uint32_t hi, lo;
        bf16_split2(A3w[k * 64 + n], A3w[(k + 1) * 64 + n], hi, lo);
        *(uint32_t*)(smem + SM_B1H + idx * 4) = hi;
        *(uint32_t*)(smem + SM_B1L + idx * 4) = lo;
    }
    for (int idx = tid; idx < 2048; idx += 256) {
        int lane = idx & 31, reg = (idx >> 5) & 1, nt = (idx >> 6) & 7, s = idx >> 9;
        int k = s * 16 + reg * 8 + 2 * (lane & 3);
        int n = nt * 8 + (lane >> 2);
        uint32_t hi, lo;
        bf16_split2(A4w[k * 64 + n], A4w[(k + 1) * 64 + n], hi, lo);
        *(uint32_t*)(smem + SM_B2H + idx * 4) = hi;
        *(uint32_t*)(smem + SM_B2L + idx * 4) = lo;
    }
    if (tid < 64) *(float*)(smem + SM_BIAS + tid * 4) = A4b[tid];
    __syncthreads();

    char* A1h = smem + SM_A1 + w * 8192;
    char* A1l = A1h + 4096;
    char* A2h = A1h;
    char* A2l = A1l;
    const float* biasSh = (const float*)(smem + SM_BIAS);

    int bs   = l >> 2;
    int bkhi = (l >> 1) & 1;
    int blpar= l & 1;
    int lr0 = l >> 2;
    int col0 = 2 * (l & 3);

    for (int tile = blockIdx.x; tile < NTILE_; tile += gridDim.x) {
        __syncwarp();
#pragma unroll 2
        for (int j = 0; j < 16; j++) {
            int g = tile * TILE_M + w * 16 + j;
            int e = g / 12, tt = g - e * 12;
            int bb = bi[e];
            int ns = bb * N_ + si[e], nr = bb * N_ + ri[e];
            size_t o = (size_t)tt * 128 + 4 * l;
            float4 a  = *(const float4*)(g_S1 + (size_t)ns * TH_ + o);
            float4 d  = *(const float4*)(g_S2 + (size_t)ns * TH_ + o);
            float4 c  = *(const float4*)(g_S1 + (size_t)nr * TH_ + o);
            float4 b4 = *(const float4*)(g_S2 + (size_t)nr * TH_ + o);
            float h0 = fmaxf(a.x + b4.x, 0.f) - fmaxf(c.x + d.x, 0.f);
            float h1 = fmaxf(a.y + b4.y, 0.f) - fmaxf(c.y + d.y, 0.f);
            float h2 = fmaxf(a.z + b4.z, 0.f) - fmaxf(c.z + d.z, 0.f);
            float h3 = fmaxf(a.w + b4.w, 0.f) - fmaxf(c.w + d.w, 0.f);
            uint32_t hiA, loA, hiB, loB;
            bf16_split2(h0, h1, hiA, loA);
            bf16_split2(h2, h3, hiB, loB);
            int reg = (j >> 3) + 2 * bkhi;
            int lf0 = (j & 7) * 4 + 2 * blpar;
            uint32_t word = (uint32_t)((bs * 4 + reg) * 32 + (lf0 ^ (4 * bs)));
            *(uint2*)(A1h + word * 4) = make_uint2(hiA, hiB);
            *(uint2*)(A1l + word * 4) = make_uint2(loA, loB);
        }
        __syncwarp();

        float acc[8][4];
#pragma unroll
        for (int nt = 0; nt < 8; nt++)
#pragma unroll
            for (int r = 0; r < 4; r++) acc[nt][r] = 0.f;
#pragma unroll
        for (int s = 0; s < 8; s++) {
            int lsw = l ^ (4 * s);
            uint32_t ah[4], al[4];
#pragma unroll
            for (int r = 0; r < 4; r++) {
                ah[r] = *(const uint32_t*)(A1h + ((s * 4 + r) * 32 + lsw) * 4);
                al[r] = *(const uint32_t*)(A1l + ((s * 4 + r) * 32 + lsw) * 4);
            }
#pragma unroll
            for (int nt = 0; nt < 8; nt++) {
                uint32_t boff = (uint32_t)((((s * 8 + nt) * 2) * 32 + l) * 4);
                uint32_t bh0 = *(const uint32_t*)(smem + SM_B1H + boff);
                uint32_t bh1 = *(const uint32_t*)(smem + SM_B1H + boff + 128);
                uint32_t bl0 = *(const uint32_t*)(smem + SM_B1L + boff);
                uint32_t bl1 = *(const uint32_t*)(smem + SM_B1L + boff + 128);
                mma_bf16(acc[nt][0], acc[nt][1], acc[nt][2], acc[nt][3],
                         ah[0], ah[1], ah[2], ah[3], bh0, bh1);
                mma_bf16(acc[nt][0], acc[nt][1], acc[nt][2], acc[nt][3],
                         al[0], al[1], al[2], al[3], bh0, bh1);
                mma_bf16(acc[nt][0], acc[nt][1], acc[nt][2], acc[nt][3],
                         ah[0], ah[1], ah[2], ah[3], bl0, bl1);
            }
        }
        __syncwarp();

#pragma unroll
        for (int nt = 0; nt < 8; nt++) {
            float x0 = fmaxf(acc[nt][0], 0.f), x1 = fmaxf(acc[nt][1], 0.f);
            float x2 = fmaxf(acc[nt][2], 0.f), x3 = fmaxf(acc[nt][3], 0.f);
            uint32_t hi0, lo0, hi1, lo1;
            bf16_split2(x0, x1, hi0, lo0);
            bf16_split2(x2, x3, hi1, lo1);
            int s2 = nt >> 1, khi = nt & 1;
            int lsw = l ^ (4 * s2);
            uint32_t o0 = (uint32_t)(((s2 * 4 + 2 * khi + 0) * 32 + lsw) * 4);
            uint32_t o1 = (uint32_t)(((s2 * 4 + 2 * khi + 1) * 32 + lsw) * 4);
            *(uint32_t*)(A2h + o0) = hi0;
            *(uint32_t*)(A2h + o1) = hi1;
            *(uint32_t*)(A2l + o0) = lo0;
            *(uint32_t*)(A2l + o1) = lo1;
        }
        __syncwarp();

        float vac[8][4];
#pragma unroll
        for (int nt = 0; nt < 8; nt++)
#pragma unroll
            for (int r = 0; r < 4; r++) vac[nt][r] = 0.f;
#pragma unroll
        for (int s = 0; s < 4; s++) {
            int lsw = l ^ (4 * s);
            uint32_t ah[4], al[4];
#pragma unroll
            for (int r = 0; r < 4; r++) {
                ah[r] = *(const uint32_t*)(A2h + ((s * 4 + r) * 32 + lsw) * 4);
                al[r] = *(const uint32_t*)(A2l + ((s * 4 + r) * 32 + lsw) * 4);
            }
#pragma unroll
            for (int nt = 0; nt < 8; nt++) {
                uint32_t boff = (uint32_t)((((s * 8 + nt) * 2) * 32 + l) * 4);
                uint32_t bh0 = *(const uint32_t*)(smem + SM_B2H + boff);
                uint32_t bh1 = *(const uint32_t*)(smem + SM_B2H + boff + 128);
                uint32_t bl0 = *(const uint32_t*)(smem + SM_B2L + boff);
                uint32_t bl1 = *(const uint32_t*)(smem + SM_B2L + boff + 128);
                mma_bf16(vac[nt][0], vac[nt][1], vac[nt][2], vac[nt][3],
                         ah[0], ah[1], ah[2], ah[3], bh0, bh1);
                mma_bf16(vac[nt][0], vac[nt][1], vac[nt][2], vac[nt][3],
                         al[0], al[1], al[2], al[3], bh0, bh1);
                mma_bf16(vac[nt][0], vac[nt][1], vac[nt][2], vac[nt][3],
                         ah[0], ah[1], ah[2], ah[3], bl0, bl1);
            }
        }

        {
            int g0 = tile * TILE_M + w * 16 + lr0;
            int e0 = g0 / 12, t0 = g0 - 12 * e0;
            int g1 = g0 + 8;
            int e1 = g1 / 12, t1 = g1 - 12 * e1;
            float* ob0 = outv + (size_t)e0 * TD_ + t0 * 64;
            float* ob1 = outv + (size_t)e1 * TD_ + t1 * 64;
#pragma unroll
            for (int nt = 0; nt < 8; nt++) {
                int c = nt * 8 + col0;
                float bz0 = biasSh[c], bz1 = biasSh[c + 1];
                *(float2*)(ob0 + c) = make_float2(vac[nt][0] + bz0, vac[nt][1] + bz1);
                *(float2*)(ob1 + c) = make_float2(vac[nt][2] + bz0, vac[nt][3] + bz1);
            }
        }
    }
}

// ---------------- softmax: one block/segment, 192 thr, float4 lanes, exp cached ----------------
#define SMAX_SMEM (SMAX_CAP * TD_ * 4)   // 98,304 B
__global__ void __launch_bounds__(192)
k_softmax(float* __restrict__ v) {
    extern __shared__ float4 buf4[];
    int seg = blockIdx.x;
    int beg = g_off[seg], end = g_off[seg + 1];
    int n = end - beg;
    if (n <= 0) return;
    int c = threadIdx.x;          // float4 column index 0..191
    if (n <= SMAX_CAP) {
        float4 s4 = make_float4(0.f, 0.f, 0.f, 0.f);
        for (int i = 0; i < n; i++) {
            const float4 vp = *((const float4*)(v + (size_t)g_csr_s[beg + i] * TD_) + c);
            float4 e;
            e.x = __expf(vp.x); e.y = __expf(vp.y); e.z = __expf(vp.z); e.w = __expf(vp.w);
            buf4[i * TD4_ + c] = e;
            s4.x += e.x; s4.y += e.y; s4.z += e.z; s4.w += e.w;
        }
        float4 r4;
        r4.x = 1.f / (s4.x + 1e-12f); r4.y = 1.f / (s4.y + 1e-12f);
        r4.z = 1.f / (s4.z + 1e-12f); r4.w = 1.f / (s4.w + 1e-12f);
        for (int i = 0; i < n; i++) {
            float4 e = buf4[i * TD4_ + c];
            e.x *= r4.x; e.y *= r4.y; e.z *= r4.z; e.w *= r4.w;
            *((float4*)(v + (size_t)g_csr_s[beg + i] * TD_) + c) = e;
        }
    } else {
        float4 s4 = make_float4(0.f, 0.f, 0.f, 0.f);
        for (int i = beg; i < end; i++) {
            const float4 vp = *((const float4*)(v + (size_t)g_csr_s[i] * TD_) + c);
            s4.x += __expf(vp.x); s4.y += __expf(vp.y);
            s4.z += __expf(vp.z); s4.w += __expf(vp.w);
        }
        float4 r4;
        r4.x = 1.f / (s4.x + 1e-12f); r4.y = 1.f / (s4.y + 1e-12f);
        r4.z = 1.f / (s4.z + 1e-12f); r4.w = 1.f / (s4.w + 1e-12f);
        for (int i = beg; i < end; i++) {
            float4* vp = (float4*)(v + (size_t)g_csr_s[i] * TD_) + c;
            float4 x = *vp;
            x.x = __expf(x.x) * r4.x; x.y = __expf(x.y) * r4.y;
            x.z = __expf(x.z) * r4.z; x.w = __expf(x.w) * r4.w;
            *vp = x;
        }
    }
}

// ---------------- per-receiver aggregation + x update (192 thr, float4 lanes) ----------------
__global__ void __launch_bounds__(192)
k_aggregate(const float* __restrict__ x, const float* __restrict__ v,
            const int* __restrict__ bi, const int* __restrict__ si,
            float* __restrict__ outx) {
    int seg = blockIdx.x;
    int c = threadIdx.x;          // float4 column 0..191
    int beg = g_off[(SEG_ + 1) + seg], end = g_off[(SEG_ + 1) + seg + 1];
    float4 a4 = make_float4(0.f, 0.f, 0.f, 0.f);
    for (int i = beg; i < end; i++) {
        int e = g_csr_r[i];
        int ns = bi[e] * N_ + si[e];
        const float4 vp = *((const float4*)(v + (size_t)e * TD_) + c);
        const float4 xs = *((const float4*)(x + (size_t)ns * TD_) + c);
        a4.x = fmaf(vp.x, xs.x, a4.x);
        a4.y = fmaf(vp.y, xs.y, a4.y);
        a4.z = fmaf(vp.z, xs.z, a4.z);
        a4.w = fmaf(vp.w, xs.w, a4.w);
    }
    const float4 xr = *((const float4*)(x + (size_t)seg * TD_) + c);
    float4 o;
    o.x = xr.x + 0.1f * (a4.x - xr.x);
    o.y = xr.y + 0.1f * (a4.y - xr.y);
    o.z = xr.z + 0.1f * (a4.z - xr.z);
    o.w = xr.w + 0.1f * (a4.w - xr.w);
    *((float4*)(outx + (size_t)seg * TD_) + c) = o;
}

// ---------------- launch ----------------
extern "C" void kernel_launch(void* const* d_in, const int* in_sizes, int n_in,
                              void* d_out, int out_size) {
    const float* x   = (const float*)d_in[0];
    const int*   bi  = (const int*)d_in[1];
    const int*   si  = (const int*)d_in[2];
    const int*   ri  = (const int*)d_in[3];
    const float* A1w = (const float*)d_in[4];
    const float* A1b = (const float*)d_in[5];
    const float* A2w = (const float*)d_in[6];
    const float* A2b = (const float*)d_in[7];
    const float* A3w = (const float*)d_in[8];
    // d_in[9] = A3_b: cancels in z_ij - z_ji
    const float* A4w = (const float*)d_in[10];
    const float* A4b = (const float*)d_in[11];

    float* outx = (float*)d_out;
    float* outv = outx + (size_t)ROWS_ * D_;

    cudaFuncSetAttribute(k_nodeproj, cudaFuncAttributeMaxDynamicSharedMemorySize, NPM_SMEM);
    cudaFuncSetAttribute(k_edge_mma, cudaFuncAttributeMaxDynamicSharedMemorySize, EM_SMEM);
    cudaFuncSetAttribute(k_softmax,  cudaFuncAttributeMaxDynamicSharedMemorySize, SMAX_SMEM);

    // edge at kernel-launch index 3 for ncu capture
    k_zero<<<32, 256>>>();                                            // 0
    k_count<<<(E_ + 255) / 256, 256>>>(bi, si, ri);                   // 1
    k_nodeproj<<<ROWS_ / 128, 256, NPM_SMEM>>>(x, A1w, A1b, A2w, A2b);// 2
    k_edge_mma<<<296, 256, EM_SMEM>>>(bi, si, ri, A3w, A4w, A4b, outv);// 3 (profiled)
    k_scan2<<<2, 1024>>>();                                           // 4
    k_scatter<<<(E_ + 255) / 256, 256>>>(bi, si, ri);                 // 5
    k_softmax<<<SEG_, 192, SMAX_SMEM>>>(outv);                        // 6
    k_aggregate<<<SEG_, 192>>>(x, outv, bi, si, outx);                // 7
}

// round 14
// speedup vs baseline: 1.1424x; 1.0860x over previous
#include <cuda_runtime.h>
#include <cuda_bf16.h>
#include <cstdint>

#define B_    4
#define N_    1000
#define T_    12
#define D_    64
#define HID_  128
#define EF_   64
#define E_    64000
#define SEG_  (B_*N_)       // 4000
#define ROWS_ (SEG_*T_)     // 48000
#define TD_   (T_*D_)       // 768
#define TH_   (T_*HID_)     // 1536
#define MROWS_ (E_*T_)      // 768000
#define TILE_M 128
#define NTILE_ (MROWS_/TILE_M)   // 6000
#define SMAX_CAP 32

// ---------------- device scratch ----------------
__device__ float g_S1[ROWS_ * HID_];
__device__ float g_S2[ROWS_ * HID_];
__device__ int   g_cnt[2 * SEG_];
__device__ int   g_off[2 * (SEG_ + 1)];
__device__ int   g_cur[2 * SEG_];
__device__ int   g_csr_s[E_];
__device__ int   g_csr_r[E_];

// ---------------- mma.sync bf16 (sm_80+ legacy tensor path) ----------------
__device__ __forceinline__ void mma_bf16(float& d0, float& d1, float& d2, float& d3,
                                         uint32_t a0, uint32_t a1, uint32_t a2, uint32_t a3,
                                         uint32_t b0, uint32_t b1) {
    asm("mma.sync.aligned.m16n8k16.row.col.f32.bf16.bf16.f32 "
        "{%0,%1,%2,%3},{%4,%5,%6,%7},{%8,%9},{%0,%1,%2,%3};"
        : "+f"(d0), "+f"(d1), "+f"(d2), "+f"(d3)
        : "r"(a0), "r"(a1), "r"(a2), "r"(a3), "r"(b0), "r"(b1));
}

__device__ __forceinline__ void bf16_split2(float x, float y, uint32_t& hi, uint32_t& lo) {
    __nv_bfloat162 h2 = __float22bfloat162_rn(make_float2(x, y));
    hi = *(uint32_t*)&h2;
    float2 hf = __bfloat1622float2(h2);
    __nv_bfloat162 l2 = __float22bfloat162_rn(make_float2(x - hf.x, y - hf.y));
    lo = *(uint32_t*)&l2;
}

// ---------------- CSR build (parallel) ----------------
__global__ void k_zero() {
    int i = blockIdx.x * blockDim.x + threadIdx.x;
    if (i < 2 * SEG_) g_cnt[i] = 0;
}

__global__ void k_count(const int* __restrict__ bi, const int* __restrict__ si,
                        const int* __restrict__ ri) {
    int e = blockIdx.x * blockDim.x + threadIdx.x;
    if (e >= E_) return;
    int b = bi[e];
    atomicAdd(&g_cnt[b * N_ + si[e]], 1);
    atomicAdd(&g_cnt[SEG_ + b * N_ + ri[e]], 1);
}

__global__ void k_scan2() {
    int which = blockIdx.x;
    const int* cnt = g_cnt + which * SEG_;
    int* off = g_off + which * (SEG_ + 1);
    int* cur = g_cur + which * SEG_;
    __shared__ int part[1024];
    int tid = threadIdx.x;
    int l[4]; int s = 0;
#pragma unroll
    for (int j = 0; j < 4; j++) {
        int idx = tid * 4 + j;
        l[j] = (idx < SEG_) ? cnt[idx] : 0;
        s += l[j];
    }
    part[tid] = s;
    __syncthreads();
    for (int o = 1; o < 1024; o <<= 1) {
        int v = part[tid];
        int a = (tid >= o) ? part[tid - o] : 0;
        __syncthreads();
        part[tid] = v + a;
        __syncthreads();
    }
    int run = (tid > 0) ? part[tid - 1] : 0;
#pragma unroll
    for (int j = 0; j < 4; j++) {
        int idx = tid * 4 + j;
        if (idx < SEG_) { off[idx] = run; cur[idx] = run; run += l[j]; }
    }
    if (tid == 1023) off[SEG_] = part[1023];
}

__global__ void k_scatter(const int* __restrict__ bi, const int* __restrict__ si,
                          const int* __restrict__ ri) {
    int e = blockIdx.x * blockDim.x + threadIdx.x;
    if (e >= E_) return;
    int b = bi[e];
    int ps = atomicAdd(&g_cur[b * N_ + si[e]], 1);
    g_csr_s[ps] = e;
    int pr = atomicAdd(&g_cur[SEG_ + b * N_ + ri[e]], 1);
    g_csr_r[pr] = e;
}

// ---------------- node projection via mma (S1 = x@A1 + b12, S2 = x@A2) ----------------
#define NPM_B1H 0               // [4s][16nt][2reg][32] u32 = 16 KB
#define NPM_B1L 16384
#define NPM_B2H 32768
#define NPM_B2L 49152
#define NPM_BIAS 65536          // 128 floats
#define NPM_A   66048           // per warp 4 KB (hi 2 + lo 2), 8 warps
#define NPM_SMEM (NPM_A + 8*4096)   // 98,816 B

__global__ void __launch_bounds__(256)
k_nodeproj(const float* __restrict__ x,
           const float* __restrict__ A1w, const float* __restrict__ A1b,
           const float* __restrict__ A2w, const float* __restrict__ A2b) {
    extern __shared__ char smem[];
    int tid = threadIdx.x;
    int w = tid >> 5;
    int l = tid & 31;

    // layout word = ((s*16 + nt)*2 + reg)*32 + lane  ->  s = idx >> 10
    for (int idx = tid; idx < 4096; idx += 256) {
        int lane = idx & 31, reg = (idx >> 5) & 1, nt = (idx >> 6) & 15, s = idx >> 10;
        int k = s * 16 + reg * 8 + 2 * (lane & 3);
        int n = nt * 8 + (lane >> 2);
        uint32_t hi, lo;
        bf16_split2(A1w[k * 128 + n], A1w[(k + 1) * 128 + n], hi, lo);
        *(uint32_t*)(smem + NPM_B1H + idx * 4) = hi;
        *(uint32_t*)(smem + NPM_B1L + idx * 4) = lo;
        bf16_split2(A2w[k * 128 + n], A2w[(k + 1) * 128 + n], hi, lo);
        *(uint32_t*)(smem + NPM_B2H + idx * 4) = hi;
        *(uint32_t*)(smem + NPM_B2L + idx * 4) = lo;
    }
    if (tid < 128) *(float*)(smem + NPM_BIAS + tid * 4) = A1b[tid] + A2b[tid];
    __syncthreads();

    char* Ah = smem + NPM_A + w * 4096;
    char* Al = Ah + 2048;
    const float* biasSh = (const float*)(smem + NPM_BIAS);

    int rowBase = blockIdx.x * 128 + w * 16;
    {
        int s = l >> 3;
        int khi = (l >> 2) & 1;
        int lf_lo = l & 3;
#pragma unroll 4
        for (int j = 0; j < 16; j++) {
            float2 xv = *(const float2*)(x + (size_t)(rowBase + j) * 64 + 2 * l);
            uint32_t hi, lo;
            bf16_split2(xv.x, xv.y, hi, lo);
            int reg = (j >> 3) + 2 * khi;
            int lane_f = (j & 7) * 4 + lf_lo;
            uint32_t word = (uint32_t)((s * 4 + reg) * 32 + (lane_f ^ (4 * s)));
            *(uint32_t*)(Ah + word * 4) = hi;
            *(uint32_t*)(Al + word * 4) = lo;
        }
    }
    __syncwarp();

    int lr0 = l >> 2;
    int col0 = 2 * (l & 3);

#pragma unroll
    for (int m = 0; m < 2; m++) {
        const char* BH = smem + (m == 0 ? NPM_B1H : NPM_B2H);
        const char* BL = smem + (m == 0 ? NPM_B1L : NPM_B2L);
        float acc[16][4];
#pragma unroll
        for (int nt = 0; nt < 16; nt++)
#pragma unroll
            for (int r = 0; r < 4; r++) acc[nt][r] = 0.f;
#pragma unroll
        for (int s = 0; s < 4; s++) {
            int lsw = l ^ (4 * s);
            uint32_t ah[4], al[4];
#pragma unroll
            for (int r = 0; r < 4; r++) {
                ah[r] = *(const uint32_t*)(Ah + ((s * 4 + r) * 32 + lsw) * 4);
                al[r] = *(const uint32_t*)(Al + ((s * 4 + r) * 32 + lsw) * 4);
            }
#pragma unroll
            for (int nt = 0; nt < 16; nt++) {
                uint32_t boff = (uint32_t)((((s * 16 + nt) * 2) * 32 + l) * 4);
                uint32_t bh0 = *(const uint32_t*)(BH + boff);
                uint32_t bh1 = *(const uint32_t*)(BH + boff + 128);
                uint32_t bl0 = *(const uint32_t*)(BL + boff);
                uint32_t bl1 = *(const uint32_t*)(BL + boff + 128);
                mma_bf16(acc[nt][0], acc[nt][1], acc[nt][2], acc[nt][3],
                         ah[0], ah[1], ah[2], ah[3], bh0, bh1);
                mma_bf16(acc[nt][0], acc[nt][1], acc[nt][2], acc[nt][3],
                         al[0], al[1], al[2], al[3], bh0, bh1);
                mma_bf16(acc[nt][0], acc[nt][1], acc[nt][2], acc[nt][3],
                         ah[0], ah[1], ah[2], ah[3], bl0, bl1);
            }
        }
        float* out = (m == 0) ? g_S1 : g_S2;
        float* ob0 = out + (size_t)(rowBase + lr0) * 128;
        float* ob1 = out + (size_t)(rowBase + lr0 + 8) * 128;
#pragma unroll
        for (int nt = 0; nt < 16; nt++) {
            int c = nt * 8 + col0;
            float bz0 = (m == 0) ? biasSh[c] : 0.f;
            float bz1 = (m == 0) ? biasSh[c + 1] : 0.f;
            *(float2*)(ob0 + c) = make_float2(acc[nt][0] + bz0, acc[nt][1] + bz1);
            *(float2*)(ob1 + c) = make_float2(acc[nt][2] + bz0, acc[nt][3] + bz1);
        }
    }
}

// ---------------- tensor-core edge kernel (R11 proven config: 8 warps x 16 rows) ----------------
#define SM_B1H  0
#define SM_B1L  16384
#define SM_B2H  32768
#define SM_B2L  40960
#define SM_BIAS 49152
#define SM_A1   49408
#define EM_SMEM (SM_A1 + 8*8192)             // 114,944 B

__global__ void __launch_bounds__(256)
k_edge_mma(const int* __restrict__ bi, const int* __restrict__ si,
           const int* __restrict__ ri,
           const float* __restrict__ A3w, const float* __restrict__ A4w,
           const float* __restrict__ A4b, float* __restrict__ outv) {
    extern __shared__ char smem[];
    int tid = threadIdx.x;
    int w = tid >> 5;
    int l = tid & 31;

    for (int idx = tid; idx < 4096; idx += 256) {
        int lane = idx & 31, reg = (idx >> 5) & 1, nt = (idx >> 6) & 7, s = idx >> 9;
        int k = s * 16 + reg * 8 + 2 * (lane & 3);
        int n = nt * 8 + (lane >> 2);
        uint32_t hi, lo;
        bf16_split2(A3w[k * 64 + n], A3w[(k + 1) * 64 + n], hi, lo);
        *(uint32_t*)(smem + SM_B1H + idx * 4) = hi;
        *(uint32_t*)(smem + SM_B1L + idx * 4) = lo;
    }
    for (int idx = tid; idx < 2048; idx += 256) {
        int lane = idx & 31, reg = (idx >> 5) & 1, nt = (idx >> 6) & 7, s = idx >> 9;
        int k = s * 16 + reg * 8 + 2 * (lane & 3);
        int n = nt * 8 + (lane >> 2);
        uint32_t hi, lo;
        bf16_split2(A4w[k * 64 + n], A4w[(k + 1) * 64 + n], hi, lo);
        *(uint32_t*)(smem + SM_B2H + idx * 4) = hi;
        *(uint32_t*)(smem + SM_B2L + idx * 4) = lo;
    }
    if (tid < 64) *(float*)(smem + SM_BIAS + tid * 4) = A4b[tid];
    __syncthreads();

    char* A1h = smem + SM_A1 + w * 8192;
    char* A1l = A1h + 4096;
    char* A2h = A1h;
    char* A2l = A1l;
    const float* biasSh = (const float*)(smem + SM_BIAS);

    int bs   = l >> 2;
    int bkhi = (l >> 1) & 1;
    int blpar= l & 1;
    int lr0 = l >> 2;
    int col0 = 2 * (l & 3);

    for (int tile = blockIdx.x; tile < NTILE_; tile += gridDim.x) {
        __syncwarp();
#pragma unroll 2
        for (int j = 0; j < 16; j++) {
            int g = tile * TILE_M + w * 16 + j;
            int e = g / 12, tt = g - e * 12;
            int bb = bi[e];
            int ns = bb * N_ + si[e], nr = bb * N_ + ri[e];
            size_t o = (size_t)tt * 128 + 4 * l;
            float4 a  = *(const float4*)(g_S1 + (size_t)ns * TH_ + o);
            float4 d  = *(const float4*)(g_S2 + (size_t)ns * TH_ + o);
            float4 c  = *(const float4*)(g_S1 + (size_t)nr * TH_ + o);
            float4 b4 = *(const float4*)(g_S2 + (size_t)nr * TH_ + o);
            float h0 = fmaxf(a.x + b4.x, 0.f) - fmaxf(c.x + d.x, 0.f);
            float h1 = fmaxf(a.y + b4.y, 0.f) - fmaxf(c.y + d.y, 0.f);
            float h2 = fmaxf(a.z + b4.z, 0.f) - fmaxf(c.z + d.z, 0.f);
            float h3 = fmaxf(a.w + b4.w, 0.f) - fmaxf(c.w + d.w, 0.f);
            uint32_t hiA, loA, hiB, loB;
            bf16_split2(h0, h1, hiA, loA);
            bf16_split2(h2, h3, hiB, loB);
            int reg = (j >> 3) + 2 * bkhi;
            int lf0 = (j & 7) * 4 + 2 * blpar;
            uint32_t word = (uint32_t)((bs * 4 + reg) * 32 + (lf0 ^ (4 * bs)));
            *(uint2*)(A1h + word * 4) = make_uint2(hiA, hiB);
            *(uint2*)(A1l + word * 4) = make_uint2(loA, loB);
        }
        __syncwarp();

        float acc[8][4];
#pragma unroll
        for (int nt = 0; nt < 8; nt++)
#pragma unroll
            for (int r = 0; r < 4; r++) acc[nt][r] = 0.f;
#pragma unroll
        for (int s = 0; s < 8; s++) {
            int lsw = l ^ (4 * s);
            uint32_t ah[4], al[4];
#pragma unroll
            for (int r = 0; r < 4; r++) {
                ah[r] = *(const uint32_t*)(A1h + ((s * 4 + r) * 32 + lsw) * 4);
                al[r] = *(const uint32_t*)(A1l + ((s * 4 + r) * 32 + lsw) * 4);
            }
#pragma unroll
            for (int nt = 0; nt < 8; nt++) {
                uint32_t boff = (uint32_t)((((s * 8 + nt) * 2) * 32 + l) * 4);
                uint32_t bh0 = *(const uint32_t*)(smem + SM_B1H + boff);
                uint32_t bh1 = *(const uint32_t*)(smem + SM_B1H + boff + 128);
                uint32_t bl0 = *(const uint32_t*)(smem + SM_B1L + boff);
                uint32_t bl1 = *(const uint32_t*)(smem + SM_B1L + boff + 128);
                mma_bf16(acc[nt][0], acc[nt][1], acc[nt][2], acc[nt][3],
                         ah[0], ah[1], ah[2], ah[3], bh0, bh1);
                mma_bf16(acc[nt][0], acc[nt][1], acc[nt][2], acc[nt][3],
                         al[0], al[1], al[2], al[3], bh0, bh1);
                mma_bf16(acc[nt][0], acc[nt][1], acc[nt][2], acc[nt][3],
                         ah[0], ah[1], ah[2], ah[3], bl0, bl1);
            }
        }
        __syncwarp();

#pragma unroll
        for (int nt = 0; nt < 8; nt++) {
            float x0 = fmaxf(acc[nt][0], 0.f), x1 = fmaxf(acc[nt][1], 0.f);
            float x2 = fmaxf(acc[nt][2], 0.f), x3 = fmaxf(acc[nt][3], 0.f);
            uint32_t hi0, lo0, hi1, lo1;
            bf16_split2(x0, x1, hi0, lo0);
            bf16_split2(x2, x3, hi1, lo1);
            int s2 = nt >> 1, khi = nt & 1;
            int lsw = l ^ (4 * s2);
            uint32_t o0 = (uint32_t)(((s2 * 4 + 2 * khi + 0) * 32 + lsw) * 4);
            uint32_t o1 = (uint32_t)(((s2 * 4 + 2 * khi + 1) * 32 + lsw) * 4);
            *(uint32_t*)(A2h + o0) = hi0;
            *(uint32_t*)(A2h + o1) = hi1;
            *(uint32_t*)(A2l + o0) = lo0;
            *(uint32_t*)(A2l + o1) = lo1;
        }
        __syncwarp();

        float vac[8][4];
#pragma unroll
        for (int nt = 0; nt < 8; nt++)
#pragma unroll
            for (int r = 0; r < 4; r++) vac[nt][r] = 0.f;
#pragma unroll
        for (int s = 0; s < 4; s++) {
            int lsw = l ^ (4 * s);
            uint32_t ah[4], al[4];
#pragma unroll
            for (int r = 0; r < 4; r++) {
                ah[r] = *(const uint32_t*)(A2h + ((s * 4 + r) * 32 + lsw) * 4);
                al[r] = *(const uint32_t*)(A2l + ((s * 4 + r) * 32 + lsw) * 4);
            }
#pragma unroll
            for (int nt = 0; nt < 8; nt++) {
                uint32_t boff = (uint32_t)((((s * 8 + nt) * 2) * 32 + l) * 4);
                uint32_t bh0 = *(const uint32_t*)(smem + SM_B2H + boff);
                uint32_t bh1 = *(const uint32_t*)(smem + SM_B2H + boff + 128);
                uint32_t bl0 = *(const uint32_t*)(smem + SM_B2L + boff);
                uint32_t bl1 = *(const uint32_t*)(smem + SM_B2L + boff + 128);
                mma_bf16(vac[nt][0], vac[nt][1], vac[nt][2], vac[nt][3],
                         ah[0], ah[1], ah[2], ah[3], bh0, bh1);
                mma_bf16(vac[nt][0], vac[nt][1], vac[nt][2], vac[nt][3],
                         al[0], al[1], al[2], al[3], bh0, bh1);
                mma_bf16(vac[nt][0], vac[nt][1], vac[nt][2], vac[nt][3],
                         ah[0], ah[1], ah[2], ah[3], bl0, bl1);
            }
        }

        {
            int g0 = tile * TILE_M + w * 16 + lr0;
            int e0 = g0 / 12, t0 = g0 - 12 * e0;
            int g1 = g0 + 8;
            int e1 = g1 / 12, t1 = g1 - 12 * e1;
            float* ob0 = outv + (size_t)e0 * TD_ + t0 * 64;
            float* ob1 = outv + (size_t)e1 * TD_ + t1 * 64;
#pragma unroll
            for (int nt = 0; nt < 8; nt++) {
                int c = nt * 8 + col0;
                float bz0 = biasSh[c], bz1 = biasSh[c + 1];
                *(float2*)(ob0 + c) = make_float2(vac[nt][0] + bz0, vac[nt][1] + bz1);
                *(float2*)(ob1 + c) = make_float2(vac[nt][2] + bz0, vac[nt][3] + bz1);
            }
        }
    }
}

// ---------------- softmax: one block/segment, 256 thr, exp cached, unroll-2 MLP ----------------
#define SMAX_SMEM (SMAX_CAP * TD_ * 4)   // 98,304 B
__global__ void __launch_bounds__(256)
k_softmax(float* __restrict__ v) {
    extern __shared__ float buf[];
    int seg = blockIdx.x;
    int beg = g_off[seg], end = g_off[seg + 1];
    int n = end - beg;
    if (n <= 0) return;
    int tid = threadIdx.x;
    int c0 = tid, c1 = tid + 256, c2 = tid + 512;
    if (n <= SMAX_CAP) {
        float s0 = 0.f, s1 = 0.f, s2 = 0.f;
        int i = 0;
        for (; i + 2 <= n; i += 2) {
            const float* vpA = v + (size_t)g_csr_s[beg + i] * TD_;
            const float* vpB = v + (size_t)g_csr_s[beg + i + 1] * TD_;
            float a0 = vpA[c0], a1 = vpA[c1], a2 = vpA[c2];
            float b0 = vpB[c0], b1 = vpB[c1], b2 = vpB[c2];
            float eA0 = __expf(a0), eA1 = __expf(a1), eA2 = __expf(a2);
            float eB0 = __expf(b0), eB1 = __expf(b1), eB2 = __expf(b2);
            buf[i * TD_ + c0] = eA0; buf[i * TD_ + c1] = eA1; buf[i * TD_ + c2] = eA2;
            buf[(i + 1) * TD_ + c0] = eB0; buf[(i + 1) * TD_ + c1] = eB1; buf[(i + 1) * TD_ + c2] = eB2;
            s0 += eA0 + eB0; s1 += eA1 + eB1; s2 += eA2 + eB2;
        }
        if (i < n) {
            const float* vp = v + (size_t)g_csr_s[beg + i] * TD_;
            float e0 = __expf(vp[c0]), e1 = __expf(vp[c1]), e2 = __expf(vp[c2]);
            buf[i * TD_ + c0] = e0; buf[i * TD_ + c1] = e1; buf[i * TD_ + c2] = e2;
            s0 += e0; s1 += e1; s2 += e2;
        }
        float r0 = 1.f / (s0 + 1e-12f), r1 = 1.f / (s1 + 1e-12f), r2 = 1.f / (s2 + 1e-12f);
        for (int j = 0; j < n; j++) {
            float* vp = v + (size_t)g_csr_s[beg + j] * TD_;
            vp[c0] = buf[j * TD_ + c0] * r0;
            vp[c1] = buf[j * TD_ + c1] * r1;
            vp[c2] = buf[j * TD_ + c2] * r2;
        }
    } else {
        float s0 = 0.f, s1 = 0.f, s2 = 0.f;
        for (int i = beg; i < end; i++) {
            const float* vp = v + (size_t)g_csr_s[i] * TD_;
            s0 += __expf(vp[c0]); s1 += __expf(vp[c1]); s2 += __expf(vp[c2]);
        }
        float r0 = 1.f / (s0 + 1e-12f), r1 = 1.f / (s1 + 1e-12f), r2 = 1.f / (s2 + 1e-12f);
        for (int i = beg; i < end; i++) {
            float* vp = v + (size_t)g_csr_s[i] * TD_;
            vp[c0] = __expf(vp[c0]) * r0;
            vp[c1] = __expf(vp[c1]) * r1;
            vp[c2] = __expf(vp[c2]) * r2;
        }
    }
}

// ---------------- per-receiver aggregation + x update (unroll-2 MLP) ----------------
__global__ void __launch_bounds__(256)
k_aggregate(const float* __restrict__ x, const float* __restrict__ v,
            const int* __restrict__ bi, const int* __restrict__ si,
            float* __restrict__ outx) {
    int seg = blockIdx.x;
    int tid = threadIdx.x;
    int beg = g_off[(SEG_ + 1) + seg], end = g_off[(SEG_ + 1) + seg + 1];
    int c0 = tid, c1 = tid + 256, c2 = tid + 512;
    float a0 = 0.f, a1 = 0.f, a2 = 0.f;
    float b0 = 0.f, b1 = 0.f, b2 = 0.f;
    int i = beg;
    for (; i + 2 <= end; i += 2) {
        int eA = g_csr_r[i], eB = g_csr_r[i + 1];
        int nsA = bi[eA] * N_ + si[eA];
        int nsB = bi[eB] * N_ + si[eB];
        const float* vpA = v + (size_t)eA * TD_;
        const float* xsA = x + (size_t)nsA * TD_;
        const float* vpB = v + (size_t)eB * TD_;
        const float* xsB = x + (size_t)nsB * TD_;
        float vA0 = vpA[c0], vA1 = vpA[c1], vA2 = vpA[c2];
        float xA0 = xsA[c0], xA1 = xsA[c1], xA2 = xsA[c2];
        float vB0 = vpB[c0], vB1 = vpB[c1], vB2 = vpB[c2];
        float xB0 = xsB[c0], xB1 = xsB[c1], xB2 = xsB[c2];
        a0 = fmaf(vA0, xA0, a0); a1 = fmaf(vA1, xA1, a1); a2 = fmaf(vA2, xA2, a2);
        b0 = fmaf(vB0, xB0, b0); b1 = fmaf(vB1, xB1, b1); b2 = fmaf(vB2, xB2, b2);
    }
    if (i < end) {
        int e = g_csr_r[i];
        int ns = bi[e] * N_ + si[e];
        const float* vp = v + (size_t)e * TD_;
        const float* xs = x + (size_t)ns * TD_;
        a0 = fmaf(vp[c0], xs[c0], a0);
        a1 = fmaf(vp[c1], xs[c1], a1);
        a2 = fmaf(vp[c2], xs[c2], a2);
    }
    a0 += b0; a1 += b1; a2 += b2;
    const float* xr = x + (size_t)seg * TD_;
    float* o = outx + (size_t)seg * TD_;
    o[c0] = xr[c0] + 0.1f * (a0 - xr[c0]);
    o[c1] = xr[c1] + 0.1f * (a1 - xr[c1]);
    o[c2] = xr[c2] + 0.1f * (a2 - xr[c2]);
}

// ---------------- launch ----------------
extern "C" void kernel_launch(void* const* d_in, const int* in_sizes, int n_in,
                              void* d_out, int out_size) {
    const float* x   = (const float*)d_in[0];
    const int*   bi  = (const int*)d_in[1];
    const int*   si  = (const int*)d_in[2];
    const int*   ri  = (const int*)d_in[3];
    const float* A1w = (const float*)d_in[4];
    const float* A1b = (const float*)d_in[5];
    const float* A2w = (const float*)d_in[6];
    const float* A2b = (const float*)d_in[7];
    const float* A3w = (const float*)d_in[8];
    // d_in[9] = A3_b: cancels in z_ij - z_ji
    const float* A4w = (const float*)d_in[10];
    const float* A4b = (const float*)d_in[11];

    float* outx = (float*)d_out;
    float* outv = outx + (size_t)ROWS_ * D_;

    cudaFuncSetAttribute(k_nodeproj, cudaFuncAttributeMaxDynamicSharedMemorySize, NPM_SMEM);
    cudaFuncSetAttribute(k_edge_mma, cudaFuncAttributeMaxDynamicSharedMemorySize, EM_SMEM);
    cudaFuncSetAttribute(k_softmax,  cudaFuncAttributeMaxDynamicSharedMemorySize, SMAX_SMEM);

    // edge at kernel-launch index 3 for ncu capture
    k_zero<<<32, 256>>>();                                            // 0
    k_count<<<(E_ + 255) / 256, 256>>>(bi, si, ri);                   // 1
    k_nodeproj<<<ROWS_ / 128, 256, NPM_SMEM>>>(x, A1w, A1b, A2w, A2b);// 2
    k_edge_mma<<<296, 256, EM_SMEM>>>(bi, si, ri, A3w, A4w, A4b, outv);// 3 (profiled)
    k_scan2<<<2, 1024>>>();                                           // 4
    k_scatter<<<(E_ + 255) / 256, 256>>>(bi, si, ri);                 // 5
    k_softmax<<<SEG_, 256, SMAX_SMEM>>>(outv);                        // 6
    k_aggregate<<<SEG_, 256>>>(x, outv, bi, si, outx);                // 7
}

// round 15
// speedup vs baseline: 1.1580x; 1.0136x over previous
#include <cuda_runtime.h>
#include <cuda_bf16.h>
#include <cstdint>

#define B_    4
#define N_    1000
#define T_    12
#define D_    64
#define HID_  128
#define EF_   64
#define E_    64000
#define SEG_  (B_*N_)       // 4000
#define ROWS_ (SEG_*T_)     // 48000
#define TD_   (T_*D_)       // 768
#define TH_   (T_*HID_)     // 1536
#define MROWS_ (E_*T_)      // 768000
#define TILE_M 256
#define NTILE_ (MROWS_/TILE_M)   // 3000
#define SMAX_CAP 32

// ---------------- device scratch ----------------
__device__ float g_S1[ROWS_ * HID_];
__device__ float g_S2[ROWS_ * HID_];
__device__ int   g_cnt[2 * SEG_];
__device__ int   g_off[2 * (SEG_ + 1)];
__device__ int   g_cur[2 * SEG_];
__device__ int   g_csr_s[E_];
__device__ int   g_csr_r[E_];

// ---------------- mma.sync bf16 (sm_80+ legacy tensor path) ----------------
__device__ __forceinline__ void mma_bf16(float& d0, float& d1, float& d2, float& d3,
                                         uint32_t a0, uint32_t a1, uint32_t a2, uint32_t a3,
                                         uint32_t b0, uint32_t b1) {
    asm("mma.sync.aligned.m16n8k16.row.col.f32.bf16.bf16.f32 "
        "{%0,%1,%2,%3},{%4,%5,%6,%7},{%8,%9},{%0,%1,%2,%3};"
        : "+f"(d0), "+f"(d1), "+f"(d2), "+f"(d3)
        : "r"(a0), "r"(a1), "r"(a2), "r"(a3), "r"(b0), "r"(b1));
}

__device__ __forceinline__ void bf16_split2(float x, float y, uint32_t& hi, uint32_t& lo) {
    __nv_bfloat162 h2 = __float22bfloat162_rn(make_float2(x, y));
    hi = *(uint32_t*)&h2;
    float2 hf = __bfloat1622float2(h2);
    __nv_bfloat162 l2 = __float22bfloat162_rn(make_float2(x - hf.x, y - hf.y));
    lo = *(uint32_t*)&l2;
}

// ---------------- CSR build (parallel) ----------------
__global__ void k_zero() {
    int i = blockIdx.x * blockDim.x + threadIdx.x;
    if (i < 2 * SEG_) g_cnt[i] = 0;
}

__global__ void k_count(const int* __restrict__ bi, const int* __restrict__ si,
                        const int* __restrict__ ri) {
    int e = blockIdx.x * blockDim.x + threadIdx.x;
    if (e >= E_) return;
    int b = bi[e];
    atomicAdd(&g_cnt[b * N_ + si[e]], 1);
    atomicAdd(&g_cnt[SEG_ + b * N_ + ri[e]], 1);
}

__global__ void k_scan2() {
    int which = blockIdx.x;
    const int* cnt = g_cnt + which * SEG_;
    int* off = g_off + which * (SEG_ + 1);
    int* cur = g_cur + which * SEG_;
    __shared__ int part[1024];
    int tid = threadIdx.x;
    int l[4]; int s = 0;
#pragma unroll
    for (int j = 0; j < 4; j++) {
        int idx = tid * 4 + j;
        l[j] = (idx < SEG_) ? cnt[idx] : 0;
        s += l[j];
    }
    part[tid] = s;
    __syncthreads();
    for (int o = 1; o < 1024; o <<= 1) {
        int v = part[tid];
        int a = (tid >= o) ? part[tid - o] : 0;
        __syncthreads();
        part[tid] = v + a;
        __syncthreads();
    }
    int run = (tid > 0) ? part[tid - 1] : 0;
#pragma unroll
    for (int j = 0; j < 4; j++) {
        int idx = tid * 4 + j;
        if (idx < SEG_) { off[idx] = run; cur[idx] = run; run += l[j]; }
    }
    if (tid == 1023) off[SEG_] = part[1023];
}

__global__ void k_scatter(const int* __restrict__ bi, const int* __restrict__ si,
                          const int* __restrict__ ri) {
    int e = blockIdx.x * blockDim.x + threadIdx.x;
    if (e >= E_) return;
    int b = bi[e];
    int ps = atomicAdd(&g_cur[b * N_ + si[e]], 1);
    g_csr_s[ps] = e;
    int pr = atomicAdd(&g_cur[SEG_ + b * N_ + ri[e]], 1);
    g_csr_r[pr] = e;
}

// ---------------- node projection via mma (S1 = x@A1 + b12, S2 = x@A2) ----------------
#define NPM_B1H 0               // [4s][16nt][2reg][32] u32 = 16 KB
#define NPM_B1L 16384
#define NPM_B2H 32768
#define NPM_B2L 49152
#define NPM_BIAS 65536          // 128 floats
#define NPM_A   66048           // per warp 4 KB (hi 2 + lo 2), 8 warps
#define NPM_SMEM (NPM_A + 8*4096)   // 98,816 B

__global__ void __launch_bounds__(256)
k_nodeproj(const float* __restrict__ x,
           const float* __restrict__ A1w, const float* __restrict__ A1b,
           const float* __restrict__ A2w, const float* __restrict__ A2b) {
    extern __shared__ char smem[];
    int tid = threadIdx.x;
    int w = tid >> 5;
    int l = tid & 31;

    // layout word = ((s*16 + nt)*2 + reg)*32 + lane  ->  s = idx >> 10
    for (int idx = tid; idx < 4096; idx += 256) {
        int lane = idx & 31, reg = (idx >> 5) & 1, nt = (idx >> 6) & 15, s = idx >> 10;
        int k = s * 16 + reg * 8 + 2 * (lane & 3);
        int n = nt * 8 + (lane >> 2);
        uint32_t hi, lo;
        bf16_split2(A1w[k * 128 + n], A1w[(k + 1) * 128 + n], hi, lo);
        *(uint32_t*)(smem + NPM_B1H + idx * 4) = hi;
        *(uint32_t*)(smem + NPM_B1L + idx * 4) = lo;
        bf16_split2(A2w[k * 128 + n], A2w[(k + 1) * 128 + n], hi, lo);
        *(uint32_t*)(smem + NPM_B2H + idx * 4) = hi;
        *(uint32_t*)(smem + NPM_B2L + idx * 4) = lo;
    }
    if (tid < 128) *(float*)(smem + NPM_BIAS + tid * 4) = A1b[tid] + A2b[tid];
    __syncthreads();

    char* Ah = smem + NPM_A + w * 4096;
    char* Al = Ah + 2048;
    const float* biasSh = (const float*)(smem + NPM_BIAS);

    int rowBase = blockIdx.x * 128 + w * 16;
    {
        int s = l >> 3;
        int khi = (l >> 2) & 1;
        int lf_lo = l & 3;
#pragma unroll 4
        for (int j = 0; j < 16; j++) {
            float2 xv = *(const float2*)(x + (size_t)(rowBase + j) * 64 + 2 * l);
            uint32_t hi, lo;
            bf16_split2(xv.x, xv.y, hi, lo);
            int reg = (j >> 3) + 2 * khi;
            int lane_f = (j & 7) * 4 + lf_lo;
            uint32_t word = (uint32_t)((s * 4 + reg) * 32 + (lane_f ^ (4 * s)));
            *(uint32_t*)(Ah + word * 4) = hi;
            *(uint32_t*)(Al + word * 4) = lo;
        }
    }
    __syncwarp();

    int lr0 = l >> 2;
    int col0 = 2 * (l & 3);

#pragma unroll
    for (int m = 0; m < 2; m++) {
        const char* BH = smem + (m == 0 ? NPM_B1H : NPM_B2H);
        const char* BL = smem + (m == 0 ? NPM_B1L : NPM_B2L);
        float acc[16][4];
#pragma unroll
        for (int nt = 0; nt < 16; nt++)
#pragma unroll
            for (int r = 0; r < 4; r++) acc[nt][r] = 0.f;
#pragma unroll
        for (int s = 0; s < 4; s++) {
            int lsw = l ^ (4 * s);
            uint32_t ah[4], al[4];
#pragma unroll
            for (int r = 0; r < 4; r++) {
                ah[r] = *(const uint32_t*)(Ah + ((s * 4 + r) * 32 + lsw) * 4);
                al[r] = *(const uint32_t*)(Al + ((s * 4 + r) * 32 + lsw) * 4);
            }
#pragma unroll
            for (int nt = 0; nt < 16; nt++) {
                uint32_t boff = (uint32_t)((((s * 16 + nt) * 2) * 32 + l) * 4);
                uint32_t bh0 = *(const uint32_t*)(BH + boff);
                uint32_t bh1 = *(const uint32_t*)(BH + boff + 128);
                uint32_t bl0 = *(const uint32_t*)(BL + boff);
                uint32_t bl1 = *(const uint32_t*)(BL + boff + 128);
                mma_bf16(acc[nt][0], acc[nt][1], acc[nt][2], acc[nt][3],
                         ah[0], ah[1], ah[2], ah[3], bh0, bh1);
                mma_bf16(acc[nt][0], acc[nt][1], acc[nt][2], acc[nt][3],
                         al[0], al[1], al[2], al[3], bh0, bh1);
                mma_bf16(acc[nt][0], acc[nt][1], acc[nt][2], acc[nt][3],
                         ah[0], ah[1], ah[2], ah[3], bl0, bl1);
            }
        }
        float* out = (m == 0) ? g_S1 : g_S2;
        float* ob0 = out + (size_t)(rowBase + lr0) * 128;
        float* ob1 = out + (size_t)(rowBase + lr0 + 8) * 128;
#pragma unroll
        for (int nt = 0; nt < 16; nt++) {
            int c = nt * 8 + col0;
            float bz0 = (m == 0) ? biasSh[c] : 0.f;
            float bz1 = (m == 0) ? biasSh[c + 1] : 0.f;
            *(float2*)(ob0 + c) = make_float2(acc[nt][0] + bz0, acc[nt][1] + bz1);
            *(float2*)(ob1 + c) = make_float2(acc[nt][2] + bz0, acc[nt][3] + bz1);
        }
    }
}

// ---------------- tensor-core edge kernel: 8 warps x 32 rows, K-split GEMM1 ----------------
// Per-warp A smem stays 8 KB: two 16-row sub-tiles x (hi 2 KB + lo 2 KB), covering
// one 64-wide K half at a time. B fragments loaded once per k-step serve 32 rows.
#define SM_B1H  0
#define SM_B1L  16384
#define SM_B2H  32768
#define SM_B2L  40960
#define SM_BIAS 49152
#define SM_A1   49408
#define EM_SMEM (SM_A1 + 8*8192)             // 114,944 B

__global__ void __launch_bounds__(256, 2)
k_edge_mma(const int* __restrict__ bi, const int* __restrict__ si,
           const int* __restrict__ ri,
           const float* __restrict__ A3w, const float* __restrict__ A4w,
           const float* __restrict__ A4b, float* __restrict__ outv) {
    extern __shared__ char smem[];
    int tid = threadIdx.x;
    int w = tid >> 5;
    int l = tid & 31;

    for (int idx = tid; idx < 4096; idx += 256) {
        int lane = idx & 31, reg = (idx >> 5) & 1, nt = (idx >> 6) & 7, s = idx >> 9;
        int k = s * 16 + reg * 8 + 2 * (lane & 3);
        int n = nt * 8 + (lane >> 2);
        uint32_t hi, lo;
        bf16_split2(A3w[k * 64 + n], A3w[(k + 1) * 64 + n], hi, lo);
        *(uint32_t*)(smem + SM_B1H + idx * 4) = hi;
        *(uint32_t*)(smem + SM_B1L + idx * 4) = lo;
    }
    for (int idx = tid; idx < 2048; idx += 256) {
        int lane = idx & 31, reg = (idx >> 5) & 1, nt = (idx >> 6) & 7, s = idx >> 9;
        int k = s * 16 + reg * 8 + 2 * (lane & 3);
        int n = nt * 8 + (lane >> 2);
        uint32_t hi, lo;
        bf16_split2(A4w[k * 64 + n], A4w[(k + 1) * 64 + n], hi, lo);
        *(uint32_t*)(smem + SM_B2H + idx * 4) = hi;
        *(uint32_t*)(smem + SM_B2L + idx * 4) = lo;
    }
    if (tid < 64) *(float*)(smem + SM_BIAS + tid * 4) = A4b[tid];
    __syncthreads();

    char* Abase = smem + SM_A1 + w * 8192;   // [u: 4 KB][hi 2 KB | lo 2 KB]
    const float* biasSh = (const float*)(smem + SM_BIAS);

    // build-phase decomposition: lane covers cols 4*cq..4*cq+3 of row (2j + rp)
    int rp = l >> 4;              // row parity within LDG pair
    int cq = l & 15;              // col quarter within the 64-col half
    int bsl  = cq >> 2;           // s_local of col 4*cq
    int bkhi = (l >> 1) & 1;      // (4*cq>>3)&1
    int bpr  = 2 * (l & 1);       // k-pair base within 8-col group
    int lr0 = l >> 2;             // epilogue fragment row
    int col0 = 2 * (l & 3);

    for (int tile = blockIdx.x; tile < NTILE_; tile += gridDim.x) {
        // ---- GEMM1 with K-split: build half, multiply half, accumulate ----
        float acc[2][8][4];
#pragma unroll
        for (int u = 0; u < 2; u++)
#pragma unroll
            for (int nt = 0; nt < 8; nt++)
#pragma unroll
                for (int r = 0; r < 4; r++) acc[u][nt][r] = 0.f;

#pragma unroll
        for (int h = 0; h < 2; h++) {
            __syncwarp();
            // build: rows 0..31 (2 sub-tiles), cols 64h..64h+63
#pragma unroll
            for (int u = 0; u < 2; u++) {
                char* Ah = Abase + u * 4096;
                char* Al = Ah + 2048;
#pragma unroll 2
                for (int j = 0; j < 8; j++) {
                    int r_sub = 2 * j + rp;
                    int g = tile * TILE_M + w * 32 + u * 16 + r_sub;
                    int e = g / 12, tt = g - e * 12;
                    int bb = bi[e];
                    int ns = bb * N_ + si[e], nr = bb * N_ + ri[e];
                    size_t o = (size_t)tt * 128 + 64 * h + 4 * cq;
                    float4 a  = *(const float4*)(g_S1 + (size_t)ns * TH_ + o);
                    float4 d  = *(const float4*)(g_S2 + (size_t)ns * TH_ + o);
                    float4 c  = *(const float4*)(g_S1 + (size_t)nr * TH_ + o);
                    float4 b4 = *(const float4*)(g_S2 + (size_t)nr * TH_ + o);
                    float h0 = fmaxf(a.x + b4.x, 0.f) - fmaxf(c.x + d.x, 0.f);
                    float h1 = fmaxf(a.y + b4.y, 0.f) - fmaxf(c.y + d.y, 0.f);
                    float h2 = fmaxf(a.z + b4.z, 0.f) - fmaxf(c.z + d.z, 0.f);
                    float h3 = fmaxf(a.w + b4.w, 0.f) - fmaxf(c.w + d.w, 0.f);
                    uint32_t hiA, loA, hiB, loB;
                    bf16_split2(h0, h1, hiA, loA);
                    bf16_split2(h2, h3, hiB, loB);
                    int reg = (r_sub >> 3) + 2 * bkhi;
                    int lane_f = (r_sub & 7) * 4 + bpr;
                    uint32_t word = (uint32_t)((bsl * 4 + reg) * 32 + (lane_f ^ (4 * bsl)));
                    *(uint2*)(Ah + word * 4) = make_uint2(hiA, hiB);
                    *(uint2*)(Al + word * 4) = make_uint2(loA, loB);
                }
            }
            __syncwarp();

#pragma unroll
            for (int sl = 0; sl < 4; sl++) {
                int lsw = l ^ (4 * sl);
                uint32_t ah[2][4], al[2][4];
#pragma unroll
                for (int u = 0; u < 2; u++)
#pragma unroll
                    for (int r = 0; r < 4; r++) {
                        ah[u][r] = *(const uint32_t*)(Abase + u * 4096 + ((sl * 4 + r) * 32 + lsw) * 4);
                        al[u][r] = *(const uint32_t*)(Abase + u * 4096 + 2048 + ((sl * 4 + r) * 32 + lsw) * 4);
                    }
                int s = 4 * h + sl;
#pragma unroll
                for (int nt = 0; nt < 8; nt++) {
                    uint32_t boff = (uint32_t)((((s * 8 + nt) * 2) * 32 + l) * 4);
                    uint32_t bh0 = *(const uint32_t*)(smem + SM_B1H + boff);
                    uint32_t bh1 = *(const uint32_t*)(smem + SM_B1H + boff + 128);
                    uint32_t bl0 = *(const uint32_t*)(smem + SM_B1L + boff);
                    uint32_t bl1 = *(const uint32_t*)(smem + SM_B1L + boff + 128);
#pragma unroll
                    for (int u = 0; u < 2; u++) {
                        mma_bf16(acc[u][nt][0], acc[u][nt][1], acc[u][nt][2], acc[u][nt][3],
                                 ah[u][0], ah[u][1], ah[u][2], ah[u][3], bh0, bh1);
                        mma_bf16(acc[u][nt][0], acc[u][nt][1], acc[u][nt][2], acc[u][nt][3],
                                 al[u][0], al[u][1], al[u][2], al[u][3], bh0, bh1);
                        mma_bf16(acc[u][nt][0], acc[u][nt][1], acc[u][nt][2], acc[u][nt][3],
                                 ah[u][0], ah[u][1], ah[u][2], ah[u][3], bl0, bl1);
                    }
                }
            }
        }
        __syncwarp();

        // ---- epilogue1: relu + split -> A2 fragments (overlay, 4 KB per sub-tile) ----
#pragma unroll
        for (int u = 0; u < 2; u++) {
            char* A2h = Abase + u * 4096;
            char* A2l = A2h + 2048;
#pragma unroll
            for (int nt = 0; nt < 8; nt++) {
                float x0 = fmaxf(acc[u][nt][0], 0.f), x1 = fmaxf(acc[u][nt][1], 0.f);
                float x2 = fmaxf(acc[u][nt][2], 0.f), x3 = fmaxf(acc[u][nt][3], 0.f);
                uint32_t hi0, lo0, hi1, lo1;
                bf16_split2(x0, x1, hi0, lo0);
                bf16_split2(x2, x3, hi1, lo1);
                int s2 = nt >> 1, khi = nt & 1;
                int lsw = l ^ (4 * s2);
                uint32_t o0 = (uint32_t)(((s2 * 4 + 2 * khi + 0) * 32 + lsw) * 4);
                uint32_t o1 = (uint32_t)(((s2 * 4 + 2 * khi + 1) * 32 + lsw) * 4);
                *(uint32_t*)(A2h + o0) = hi0;
                *(uint32_t*)(A2h + o1) = hi1;
                *(uint32_t*)(A2l + o0) = lo0;
                *(uint32_t*)(A2l + o1) = lo1;
            }
        }
        __syncwarp();

        // ---- GEMM2: shared B loads across both sub-tiles ----
        float vac[2][8][4];
#pragma unroll
        for (int u = 0; u < 2; u++)
#pragma unroll
            for (int nt = 0; nt < 8; nt++)
#pragma unroll
                for (int r = 0; r < 4; r++) vac[u][nt][r] = 0.f;
#pragma unroll
        for (int s = 0; s < 4; s++) {
            int lsw = l ^ (4 * s);
            uint32_t ah[2][4], al[2][4];
#pragma unroll
            for (int u = 0; u < 2; u++)
#pragma unroll
                for (int r = 0; r < 4; r++) {
                    ah[u][r] = *(const uint32_t*)(Abase + u * 4096 + ((s * 4 + r) * 32 + lsw) * 4);
                    al[u][r] = *(const uint32_t*)(Abase + u * 4096 + 2048 + ((s * 4 + r) * 32 + lsw) * 4);
                }
#pragma unroll
            for (int nt = 0; nt < 8; nt++) {
                uint32_t boff = (uint32_t)((((s * 8 + nt) * 2) * 32 + l) * 4);
                uint32_t bh0 = *(const uint32_t*)(smem + SM_B2H + boff);
                uint32_t bh1 = *(const uint32_t*)(smem + SM_B2H + boff + 128);
                uint32_t bl0 = *(const uint32_t*)(smem + SM_B2L + boff);
                uint32_t bl1 = *(const uint32_t*)(smem + SM_B2L + boff + 128);
#pragma unroll
                for (int u = 0; u < 2; u++) {
                    mma_bf16(vac[u][nt][0], vac[u][nt][1], vac[u][nt][2], vac[u][nt][3],
                             ah[u][0], ah[u][1], ah[u][2], ah[u][3], bh0, bh1);
                    mma_bf16(vac[u][nt][0], vac[u][nt][1], vac[u][nt][2], vac[u][nt][3],
                             al[u][0], al[u][1], al[u][2], al[u][3], bh0, bh1);
                    mma_bf16(vac[u][nt][0], vac[u][nt][1], vac[u][nt][2], vac[u][nt][3],
                             ah[u][0], ah[u][1], ah[u][2], ah[u][3], bl0, bl1);
                }
            }
        }

        // ---- epilogue2: bias + STG, both sub-tiles ----
#pragma unroll
        for (int u = 0; u < 2; u++) {
            int g0 = tile * TILE_M + w * 32 + u * 16 + lr0;
            int e0 = g0 / 12, t0 = g0 - 12 * e0;
            int g1 = g0 + 8;
            int e1 = g1 / 12, t1 = g1 - 12 * e1;
            float* ob0 = outv + (size_t)e0 * TD_ + t0 * 64;
            float* ob1 = outv + (size_t)e1 * TD_ + t1 * 64;
#pragma unroll
            for (int nt = 0; nt < 8; nt++) {
                int c = nt * 8 + col0;
                float bz0 = biasSh[c], bz1 = biasSh[c + 1];
                *(float2*)(ob0 + c) = make_float2(vac[u][nt][0] + bz0, vac[u][nt][1] + bz1);
                *(float2*)(ob1 + c) = make_float2(vac[u][nt][2] + bz0, vac[u][nt][3] + bz1);
            }
        }
        __syncwarp();
    }
}

// ---------------- softmax: one block/segment, 256 thr, exp cached, unroll-2 MLP ----------------
#define SMAX_SMEM (SMAX_CAP * TD_ * 4)   // 98,304 B
__global__ void __launch_bounds__(256)
k_softmax(float* __restrict__ v) {
    extern __shared__ float buf[];
    int seg = blockIdx.x;
    int beg = g_off[seg], end = g_off[seg + 1];
    int n = end - beg;
    if (n <= 0) return;
    int tid = threadIdx.x;
    int c0 = tid, c1 = tid + 256, c2 = tid + 512;
    if (n <= SMAX_CAP) {
        float s0 = 0.f, s1 = 0.f, s2 = 0.f;
        int i = 0;
        for (; i + 2 <= n; i += 2) {
            const float* vpA = v + (size_t)g_csr_s[beg + i] * TD_;
            const float* vpB = v + (size_t)g_csr_s[beg + i + 1] * TD_;
            float a0 = vpA[c0], a1 = vpA[c1], a2 = vpA[c2];
            float b0 = vpB[c0], b1 = vpB[c1], b2 = vpB[c2];
            float eA0 = __expf(a0), eA1 = __expf(a1), eA2 = __expf(a2);
            float eB0 = __expf(b0), eB1 = __expf(b1), eB2 = __expf(b2);
            buf[i * TD_ + c0] = eA0; buf[i * TD_ + c1] = eA1; buf[i * TD_ + c2] = eA2;
            buf[(i + 1) * TD_ + c0] = eB0; buf[(i + 1) * TD_ + c1] = eB1; buf[(i + 1) * TD_ + c2] = eB2;
            s0 += eA0 + eB0; s1 += eA1 + eB1; s2 += eA2 + eB2;
        }
        if (i < n) {
            const float* vp = v + (size_t)g_csr_s[beg + i] * TD_;
            float e0 = __expf(vp[c0]), e1 = __expf(vp[c1]), e2 = __expf(vp[c2]);
            buf[i * TD_ + c0] = e0; buf[i * TD_ + c1] = e1; buf[i * TD_ + c2] = e2;
            s0 += e0; s1 += e1; s2 += e2;
        }
        float r0 = 1.f / (s0 + 1e-12f), r1 = 1.f / (s1 + 1e-12f), r2 = 1.f / (s2 + 1e-12f);
        for (int j = 0; j < n; j++) {
            float* vp = v + (size_t)g_csr_s[beg + j] * TD_;
            vp[c0] = buf[j * TD_ + c0] * r0;
            vp[c1] = buf[j * TD_ + c1] * r1;
            vp[c2] = buf[j * TD_ + c2] * r2;
        }
    } else {
        float s0 = 0.f, s1 = 0.f, s2 = 0.f;
        for (int i = beg; i < end; i++) {
            const float* vp = v + (size_t)g_csr_s[i] * TD_;
            s0 += __expf(vp[c0]); s1 += __expf(vp[c1]); s2 += __expf(vp[c2]);
        }
        float r0 = 1.f / (s0 + 1e-12f), r1 = 1.f / (s1 + 1e-12f), r2 = 1.f / (s2 + 1e-12f);
        for (int i = beg; i < end; i++) {
            float* vp = v + (size_t)g_csr_s[i] * TD_;
            vp[c0] = __expf(vp[c0]) * r0;
            vp[c1] = __expf(vp[c1]) * r1;
            vp[c2] = __expf(vp[c2]) * r2;
        }
    }
}

// ---------------- per-receiver aggregation + x update (unroll-2 MLP) ----------------
__global__ void __launch_bounds__(256)
k_aggregate(const float* __restrict__ x, const float* __restrict__ v,
            const int* __restrict__ bi, const int* __restrict__ si,
            float* __restrict__ outx) {
    int seg = blockIdx.x;
    int tid = threadIdx.x;
    int beg = g_off[(SEG_ + 1) + seg], end = g_off[(SEG_ + 1) + seg + 1];
    int c0 = tid, c1 = tid + 256, c2 = tid + 512;
    float a0 = 0.f, a1 = 0.f, a2 = 0.f;
    float b0 = 0.f, b1 = 0.f, b2 = 0.f;
    int i = beg;
    for (; i + 2 <= end; i += 2) {
        int eA = g_csr_r[i], eB = g_csr_r[i + 1];
        int nsA = bi[eA] * N_ + si[eA];
        int nsB = bi[eB] * N_ + si[eB];
        const float* vpA = v + (size_t)eA * TD_;
        const float* xsA = x + (size_t)nsA * TD_;
        const float* vpB = v + (size_t)eB * TD_;
        const float* xsB = x + (size_t)nsB * TD_;
        float vA0 = vpA[c0], vA1 = vpA[c1], vA2 = vpA[c2];
        float xA0 = xsA[c0], xA1 = xsA[c1], xA2 = xsA[c2];
        float vB0 = vpB[c0], vB1 = vpB[c1], vB2 = vpB[c2];
        float xB0 = xsB[c0], xB1 = xsB[c1], xB2 = xsB[c2];
        a0 = fmaf(vA0, xA0, a0); a1 = fmaf(vA1, xA1, a1); a2 = fmaf(vA2, xA2, a2);
        b0 = fmaf(vB0, xB0, b0); b1 = fmaf(vB1, xB1, b1); b2 = fmaf(vB2, xB2, b2);
    }
    if (i < end) {
        int e = g_csr_r[i];
        int ns = bi[e] * N_ + si[e];
        const float* vp = v + (size_t)e * TD_;
        const float* xs = x + (size_t)ns * TD_;
        a0 = fmaf(vp[c0], xs[c0], a0);
        a1 = fmaf(vp[c1], xs[c1], a1);
        a2 = fmaf(vp[c2], xs[c2], a2);
    }
    a0 += b0; a1 += b1; a2 += b2;
    const float* xr = x + (size_t)seg * TD_;
    float* o = outx + (size_t)seg * TD_;
    o[c0] = xr[c0] + 0.1f * (a0 - xr[c0]);
    o[c1] = xr[c1] + 0.1f * (a1 - xr[c1]);
    o[c2] = xr[c2] + 0.1f * (a2 - xr[c2]);
}

// ---------------- launch ----------------
extern "C" void kernel_launch(void* const* d_in, const int* in_sizes, int n_in,
                              void* d_out, int out_size) {
    const float* x   = (const float*)d_in[0];
    const int*   bi  = (const int*)d_in[1];
    const int*   si  = (const int*)d_in[2];
    const int*   ri  = (const int*)d_in[3];
    const float* A1w = (const float*)d_in[4];
    const float* A1b = (const float*)d_in[5];
    const float* A2w = (const float*)d_in[6];
    const float* A2b = (const float*)d_in[7];
    const float* A3w = (const float*)d_in[8];
    // d_in[9] = A3_b: cancels in z_ij - z_ji
    const float* A4w = (const float*)d_in[10];
    const float* A4b = (const float*)d_in[11];

    float* outx = (float*)d_out;
    float* outv = outx + (size_t)ROWS_ * D_;

    cudaFuncSetAttribute(k_nodeproj, cudaFuncAttributeMaxDynamicSharedMemorySize, NPM_SMEM);
    cudaFuncSetAttribute(k_edge_mma, cudaFuncAttributeMaxDynamicSharedMemorySize, EM_SMEM);
    cudaFuncSetAttribute(k_softmax,  cudaFuncAttributeMaxDynamicSharedMemorySize, SMAX_SMEM);

    // edge at kernel-launch index 3 for ncu capture
    k_zero<<<32, 256>>>();                                            // 0
    k_count<<<(E_ + 255) / 256, 256>>>(bi, si, ri);                   // 1
    k_nodeproj<<<ROWS_ / 128, 256, NPM_SMEM>>>(x, A1w, A1b, A2w, A2b);// 2
    k_edge_mma<<<296, 256, EM_SMEM>>>(bi, si, ri, A3w, A4w, A4b, outv);// 3 (profiled)
    k_scan2<<<2, 1024>>>();                                           // 4
    k_scatter<<<(E_ + 255) / 256, 256>>>(bi, si, ri);                 // 5
    k_softmax<<<SEG_, 256, SMAX_SMEM>>>(outv);                        // 6
    k_aggregate<<<SEG_, 256>>>(x, outv, bi, si, outx);                // 7
}

// round 16
// speedup vs baseline: 1.1642x; 1.0054x over previous
#include <cuda_runtime.h>
#include <cuda_bf16.h>
#include <cstdint>

#define B_    4
#define N_    1000
#define T_    12
#define D_    64
#define HID_  128
#define EF_   64
#define E_    64000
#define SEG_  (B_*N_)       // 4000
#define ROWS_ (SEG_*T_)     // 48000
#define TD_   (T_*D_)       // 768
#define TH_   (T_*HID_)     // 1536
#define MROWS_ (E_*T_)      // 768000
#define TILE_M 256
#define NTILE_ (MROWS_/TILE_M)   // 3000
#define SMAX_CAP 32

// ---------------- device scratch ----------------
__device__ float g_S1[ROWS_ * HID_];
__device__ float g_S2[ROWS_ * HID_];
__device__ int   g_cnt[2 * SEG_];      // loader-zeroed; k_scan2 re-zeros after use
__device__ int   g_off[2 * (SEG_ + 1)];
__device__ int   g_cur[2 * SEG_];
__device__ int   g_csr_s[E_];
__device__ int   g_csr_r[E_];

// ---------------- mma.sync bf16 (sm_80+ legacy tensor path) ----------------
__device__ __forceinline__ void mma_bf16(float& d0, float& d1, float& d2, float& d3,
                                         uint32_t a0, uint32_t a1, uint32_t a2, uint32_t a3,
                                         uint32_t b0, uint32_t b1) {
    asm("mma.sync.aligned.m16n8k16.row.col.f32.bf16.bf16.f32 "
        "{%0,%1,%2,%3},{%4,%5,%6,%7},{%8,%9},{%0,%1,%2,%3};"
        : "+f"(d0), "+f"(d1), "+f"(d2), "+f"(d3)
        : "r"(a0), "r"(a1), "r"(a2), "r"(a3), "r"(b0), "r"(b1));
}

__device__ __forceinline__ void bf16_split2(float x, float y, uint32_t& hi, uint32_t& lo) {
    __nv_bfloat162 h2 = __float22bfloat162_rn(make_float2(x, y));
    hi = *(uint32_t*)&h2;
    float2 hf = __bfloat1622float2(h2);
    __nv_bfloat162 l2 = __float22bfloat162_rn(make_float2(x - hf.x, y - hf.y));
    lo = *(uint32_t*)&l2;
}

// ---------------- CSR build (parallel; zero folded into scan) ----------------
__global__ void k_count(const int* __restrict__ bi, const int* __restrict__ si,
                        const int* __restrict__ ri) {
    int e = blockIdx.x * blockDim.x + threadIdx.x;
    if (e >= E_) return;
    int b = bi[e];
    atomicAdd(&g_cnt[b * N_ + si[e]], 1);
    atomicAdd(&g_cnt[SEG_ + b * N_ + ri[e]], 1);
}

__global__ void k_scan2() {
    int which = blockIdx.x;
    int* cnt = g_cnt + which * SEG_;
    int* off = g_off + which * (SEG_ + 1);
    int* cur = g_cur + which * SEG_;
    __shared__ int part[1024];
    int tid = threadIdx.x;
    int l[4]; int s = 0;
#pragma unroll
    for (int j = 0; j < 4; j++) {
        int idx = tid * 4 + j;
        l[j] = (idx < SEG_) ? cnt[idx] : 0;
        if (idx < SEG_) cnt[idx] = 0;    // restore invariant for next graph replay
        s += l[j];
    }
    part[tid] = s;
    __syncthreads();
    for (int o = 1; o < 1024; o <<= 1) {
        int v = part[tid];
        int a = (tid >= o) ? part[tid - o] : 0;
        __syncthreads();
        part[tid] = v + a;
        __syncthreads();
    }
    int run = (tid > 0) ? part[tid - 1] : 0;
#pragma unroll
    for (int j = 0; j < 4; j++) {
        int idx = tid * 4 + j;
        if (idx < SEG_) { off[idx] = run; cur[idx] = run; run += l[j]; }
    }
    if (tid == 1023) off[SEG_] = part[1023];
}

__global__ void k_scatter(const int* __restrict__ bi, const int* __restrict__ si,
                          const int* __restrict__ ri) {
    int e = blockIdx.x * blockDim.x + threadIdx.x;
    if (e >= E_) return;
    int b = bi[e];
    int ps = atomicAdd(&g_cur[b * N_ + si[e]], 1);
    g_csr_s[ps] = e;
    int pr = atomicAdd(&g_cur[SEG_ + b * N_ + ri[e]], 1);
    g_csr_r[pr] = e;
}

// ---------------- node projection via mma (S1 = x@A1 + b12, S2 = x@A2) ----------------
#define NPM_B1H 0
#define NPM_B1L 16384
#define NPM_B2H 32768
#define NPM_B2L 49152
#define NPM_BIAS 65536
#define NPM_A   66048
#define NPM_SMEM (NPM_A + 8*4096)   // 98,816 B

__global__ void __launch_bounds__(256)
k_nodeproj(const float* __restrict__ x,
           const float* __restrict__ A1w, const float* __restrict__ A1b,
           const float* __restrict__ A2w, const float* __restrict__ A2b) {
    extern __shared__ char smem[];
    int tid = threadIdx.x;
    int w = tid >> 5;
    int l = tid & 31;

    for (int idx = tid; idx < 4096; idx += 256) {
        int lane = idx & 31, reg = (idx >> 5) & 1, nt = (idx >> 6) & 15, s = idx >> 10;
        int k = s * 16 + reg * 8 + 2 * (lane & 3);
        int n = nt * 8 + (lane >> 2);
        uint32_t hi, lo;
        bf16_split2(A1w[k * 128 + n], A1w[(k + 1) * 128 + n], hi, lo);
        *(uint32_t*)(smem + NPM_B1H + idx * 4) = hi;
        *(uint32_t*)(smem + NPM_B1L + idx * 4) = lo;
        bf16_split2(A2w[k * 128 + n], A2w[(k + 1) * 128 + n], hi, lo);
        *(uint32_t*)(smem + NPM_B2H + idx * 4) = hi;
        *(uint32_t*)(smem + NPM_B2L + idx * 4) = lo;
    }
    if (tid < 128) *(float*)(smem + NPM_BIAS + tid * 4) = A1b[tid] + A2b[tid];
    __syncthreads();

    char* Ah = smem + NPM_A + w * 4096;
    char* Al = Ah + 2048;
    const float* biasSh = (const float*)(smem + NPM_BIAS);

    int rowBase = blockIdx.x * 128 + w * 16;
    {
        int s = l >> 3;
        int khi = (l >> 2) & 1;
        int lf_lo = l & 3;
#pragma unroll 4
        for (int j = 0; j < 16; j++) {
            float2 xv = *(const float2*)(x + (size_t)(rowBase + j) * 64 + 2 * l);
            uint32_t hi, lo;
            bf16_split2(xv.x, xv.y, hi, lo);
            int reg = (j >> 3) + 2 * khi;
            int lane_f = (j & 7) * 4 + lf_lo;
            uint32_t word = (uint32_t)((s * 4 + reg) * 32 + (lane_f ^ (4 * s)));
            *(uint32_t*)(Ah + word * 4) = hi;
            *(uint32_t*)(Al + word * 4) = lo;
        }
    }
    __syncwarp();

    int lr0 = l >> 2;
    int col0 = 2 * (l & 3);

#pragma unroll
    for (int m = 0; m < 2; m++) {
        const char* BH = smem + (m == 0 ? NPM_B1H : NPM_B2H);
        const char* BL = smem + (m == 0 ? NPM_B1L : NPM_B2L);
        float acc[16][4];
#pragma unroll
        for (int nt = 0; nt < 16; nt++)
#pragma unroll
            for (int r = 0; r < 4; r++) acc[nt][r] = 0.f;
#pragma unroll
        for (int s = 0; s < 4; s++) {
            int lsw = l ^ (4 * s);
            uint32_t ah[4], al[4];
#pragma unroll
            for (int r = 0; r < 4; r++) {
                ah[r] = *(const uint32_t*)(Ah + ((s * 4 + r) * 32 + lsw) * 4);
                al[r] = *(const uint32_t*)(Al + ((s * 4 + r) * 32 + lsw) * 4);
            }
#pragma unroll
            for (int nt = 0; nt < 16; nt++) {
                uint32_t boff = (uint32_t)((((s * 16 + nt) * 2) * 32 + l) * 4);
                uint32_t bh0 = *(const uint32_t*)(BH + boff);
                uint32_t bh1 = *(const uint32_t*)(BH + boff + 128);
                uint32_t bl0 = *(const uint32_t*)(BL + boff);
                uint32_t bl1 = *(const uint32_t*)(BL + boff + 128);
                mma_bf16(acc[nt][0], acc[nt][1], acc[nt][2], acc[nt][3],
                         ah[0], ah[1], ah[2], ah[3], bh0, bh1);
                mma_bf16(acc[nt][0], acc[nt][1], acc[nt][2], acc[nt][3],
                         al[0], al[1], al[2], al[3], bh0, bh1);
                mma_bf16(acc[nt][0], acc[nt][1], acc[nt][2], acc[nt][3],
                         ah[0], ah[1], ah[2], ah[3], bl0, bl1);
            }
        }
        float* out = (m == 0) ? g_S1 : g_S2;
        float* ob0 = out + (size_t)(rowBase + lr0) * 128;
        float* ob1 = out + (size_t)(rowBase + lr0 + 8) * 128;
#pragma unroll
        for (int nt = 0; nt < 16; nt++) {
            int c = nt * 8 + col0;
            float bz0 = (m == 0) ? biasSh[c] : 0.f;
            float bz1 = (m == 0) ? biasSh[c + 1] : 0.f;
            *(float2*)(ob0 + c) = make_float2(acc[nt][0] + bz0, acc[nt][1] + bz1);
            *(float2*)(ob1 + c) = make_float2(acc[nt][2] + bz0, acc[nt][3] + bz1);
        }
    }
}

// ---------------- tensor-core edge kernel: 8 warps x 32 rows, K-split GEMM1 (R15 proven) ----------------
#define SM_B1H  0
#define SM_B1L  16384
#define SM_B2H  32768
#define SM_B2L  40960
#define SM_BIAS 49152
#define SM_A1   49408
#define EM_SMEM (SM_A1 + 8*8192)             // 114,944 B

__global__ void __launch_bounds__(256, 2)
k_edge_mma(const int* __restrict__ bi, const int* __restrict__ si,
           const int* __restrict__ ri,
           const float* __restrict__ A3w, const float* __restrict__ A4w,
           const float* __restrict__ A4b, float* __restrict__ outv) {
    extern __shared__ char smem[];
    int tid = threadIdx.x;
    int w = tid >> 5;
    int l = tid & 31;

    for (int idx = tid; idx < 4096; idx += 256) {
        int lane = idx & 31, reg = (idx >> 5) & 1, nt = (idx >> 6) & 7, s = idx >> 9;
        int k = s * 16 + reg * 8 + 2 * (lane & 3);
        int n = nt * 8 + (lane >> 2);
        uint32_t hi, lo;
        bf16_split2(A3w[k * 64 + n], A3w[(k + 1) * 64 + n], hi, lo);
        *(uint32_t*)(smem + SM_B1H + idx * 4) = hi;
        *(uint32_t*)(smem + SM_B1L + idx * 4) = lo;
    }
    for (int idx = tid; idx < 2048; idx += 256) {
        int lane = idx & 31, reg = (idx >> 5) & 1, nt = (idx >> 6) & 7, s = idx >> 9;
        int k = s * 16 + reg * 8 + 2 * (lane & 3);
        int n = nt * 8 + (lane >> 2);
        uint32_t hi, lo;
        bf16_split2(A4w[k * 64 + n], A4w[(k + 1) * 64 + n], hi, lo);
        *(uint32_t*)(smem + SM_B2H + idx * 4) = hi;
        *(uint32_t*)(smem + SM_B2L + idx * 4) = lo;
    }
    if (tid < 64) *(float*)(smem + SM_BIAS + tid * 4) = A4b[tid];
    __syncthreads();

    char* Abase = smem + SM_A1 + w * 8192;   // [u: 4 KB][hi 2 KB | lo 2 KB]
    const float* biasSh = (const float*)(smem + SM_BIAS);

    int rp = l >> 4;
    int cq = l & 15;
    int bsl  = cq >> 2;
    int bkhi = (l >> 1) & 1;
    int bpr  = 2 * (l & 1);
    int lr0 = l >> 2;
    int col0 = 2 * (l & 3);

    for (int tile = blockIdx.x; tile < NTILE_; tile += gridDim.x) {
        float acc[2][8][4];
#pragma unroll
        for (int u = 0; u < 2; u++)
#pragma unroll
            for (int nt = 0; nt < 8; nt++)
#pragma unroll
                for (int r = 0; r < 4; r++) acc[u][nt][r] = 0.f;

#pragma unroll
        for (int h = 0; h < 2; h++) {
            __syncwarp();
#pragma unroll
            for (int u = 0; u < 2; u++) {
                char* Ah = Abase + u * 4096;
                char* Al = Ah + 2048;
#pragma unroll 2
                for (int j = 0; j < 8; j++) {
                    int r_sub = 2 * j + rp;
                    int g = tile * TILE_M + w * 32 + u * 16 + r_sub;
                    int e = g / 12, tt = g - e * 12;
                    int bb = bi[e];
                    int ns = bb * N_ + si[e], nr = bb * N_ + ri[e];
                    size_t o = (size_t)tt * 128 + 64 * h + 4 * cq;
                    float4 a  = *(const float4*)(g_S1 + (size_t)ns * TH_ + o);
                    float4 d  = *(const float4*)(g_S2 + (size_t)ns * TH_ + o);
                    float4 c  = *(const float4*)(g_S1 + (size_t)nr * TH_ + o);
                    float4 b4 = *(const float4*)(g_S2 + (size_t)nr * TH_ + o);
                    float h0 = fmaxf(a.x + b4.x, 0.f) - fmaxf(c.x + d.x, 0.f);
                    float h1 = fmaxf(a.y + b4.y, 0.f) - fmaxf(c.y + d.y, 0.f);
                    float h2 = fmaxf(a.z + b4.z, 0.f) - fmaxf(c.z + d.z, 0.f);
                    float h3 = fmaxf(a.w + b4.w, 0.f) - fmaxf(c.w + d.w, 0.f);
                    uint32_t hiA, loA, hiB, loB;
                    bf16_split2(h0, h1, hiA, loA);
                    bf16_split2(h2, h3, hiB, loB);
                    int reg = (r_sub >> 3) + 2 * bkhi;
                    int lane_f = (r_sub & 7) * 4 + bpr;
                    uint32_t word = (uint32_t)((bsl * 4 + reg) * 32 + (lane_f ^ (4 * bsl)));
                    *(uint2*)(Ah + word * 4) = make_uint2(hiA, hiB);
                    *(uint2*)(Al + word * 4) = make_uint2(loA, loB);
                }
            }
            __syncwarp();

#pragma unroll
            for (int sl = 0; sl < 4; sl++) {
                int lsw = l ^ (4 * sl);
                uint32_t ah[2][4], al[2][4];
#pragma unroll
                for (int u = 0; u < 2; u++)
#pragma unroll
                    for (int r = 0; r < 4; r++) {
                        ah[u][r] = *(const uint32_t*)(Abase + u * 4096 + ((sl * 4 + r) * 32 + lsw) * 4);
                        al[u][r] = *(const uint32_t*)(Abase + u * 4096 + 2048 + ((sl * 4 + r) * 32 + lsw) * 4);
                    }
                int s = 4 * h + sl;
#pragma unroll
                for (int nt = 0; nt < 8; nt++) {
                    uint32_t boff = (uint32_t)((((s * 8 + nt) * 2) * 32 + l) * 4);
                    uint32_t bh0 = *(const uint32_t*)(smem + SM_B1H + boff);
                    uint32_t bh1 = *(const uint32_t*)(smem + SM_B1H + boff + 128);
                    uint32_t bl0 = *(const uint32_t*)(smem + SM_B1L + boff);
                    uint32_t bl1 = *(const uint32_t*)(smem + SM_B1L + boff + 128);
#pragma unroll
                    for (int u = 0; u < 2; u++) {
                        mma_bf16(acc[u][nt][0], acc[u][nt][1], acc[u][nt][2], acc[u][nt][3],
                                 ah[u][0], ah[u][1], ah[u][2], ah[u][3], bh0, bh1);
                        mma_bf16(acc[u][nt][0], acc[u][nt][1], acc[u][nt][2], acc[u][nt][3],
                                 al[u][0], al[u][1], al[u][2], al[u][3], bh0, bh1);
                        mma_bf16(acc[u][nt][0], acc[u][nt][1], acc[u][nt][2], acc[u][nt][3],
                                 ah[u][0], ah[u][1], ah[u][2], ah[u][3], bl0, bl1);
                    }
                }
            }
        }
        __syncwarp();

#pragma unroll
        for (int u = 0; u < 2; u++) {
            char* A2h = Abase + u * 4096;
            char* A2l = A2h + 2048;
#pragma unroll
            for (int nt = 0; nt < 8; nt++) {
                float x0 = fmaxf(acc[u][nt][0], 0.f), x1 = fmaxf(acc[u][nt][1], 0.f);
                float x2 = fmaxf(acc[u][nt][2], 0.f), x3 = fmaxf(acc[u][nt][3], 0.f);
                uint32_t hi0, lo0, hi1, lo1;
                bf16_split2(x0, x1, hi0, lo0);
                bf16_split2(x2, x3, hi1, lo1);
                int s2 = nt >> 1, khi = nt & 1;
                int lsw = l ^ (4 * s2);
                uint32_t o0 = (uint32_t)(((s2 * 4 + 2 * khi + 0) * 32 + lsw) * 4);
                uint32_t o1 = (uint32_t)(((s2 * 4 + 2 * khi + 1) * 32 + lsw) * 4);
                *(uint32_t*)(A2h + o0) = hi0;
                *(uint32_t*)(A2h + o1) = hi1;
                *(uint32_t*)(A2l + o0) = lo0;
                *(uint32_t*)(A2l + o1) = lo1;
            }
        }
        __syncwarp();

        float vac[2][8][4];
#pragma unroll
        for (int u = 0; u < 2; u++)
#pragma unroll
            for (int nt = 0; nt < 8; nt++)
#pragma unroll
                for (int r = 0; r < 4; r++) vac[u][nt][r] = 0.f;
#pragma unroll
        for (int s = 0; s < 4; s++) {
            int lsw = l ^ (4 * s);
            uint32_t ah[2][4], al[2][4];
#pragma unroll
            for (int u = 0; u < 2; u++)
#pragma unroll
                for (int r = 0; r < 4; r++) {
                    ah[u][r] = *(const uint32_t*)(Abase + u * 4096 + ((s * 4 + r) * 32 + lsw) * 4);
                    al[u][r] = *(const uint32_t*)(Abase + u * 4096 + 2048 + ((s * 4 + r) * 32 + lsw) * 4);
                }
#pragma unroll
            for (int nt = 0; nt < 8; nt++) {
                uint32_t boff = (uint32_t)((((s * 8 + nt) * 2) * 32 + l) * 4);
                uint32_t bh0 = *(const uint32_t*)(smem + SM_B2H + boff);
                uint32_t bh1 = *(const uint32_t*)(smem + SM_B2H + boff + 128);
                uint32_t bl0 = *(const uint32_t*)(smem + SM_B2L + boff);
                uint32_t bl1 = *(const uint32_t*)(smem + SM_B2L + boff + 128);
#pragma unroll
                for (int u = 0; u < 2; u++) {
                    mma_bf16(vac[u][nt][0], vac[u][nt][1], vac[u][nt][2], vac[u][nt][3],
                             ah[u][0], ah[u][1], ah[u][2], ah[u][3], bh0, bh1);
                    mma_bf16(vac[u][nt][0], vac[u][nt][1], vac[u][nt][2], vac[u][nt][3],
                             al[u][0], al[u][1], al[u][2], al[u][3], bh0, bh1);
                    mma_bf16(vac[u][nt][0], vac[u][nt][1], vac[u][nt][2], vac[u][nt][3],
                             ah[u][0], ah[u][1], ah[u][2], ah[u][3], bl0, bl1);
                }
            }
        }

#pragma unroll
        for (int u = 0; u < 2; u++) {
            int g0 = tile * TILE_M + w * 32 + u * 16 + lr0;
            int e0 = g0 / 12, t0 = g0 - 12 * e0;
            int g1 = g0 + 8;
            int e1 = g1 / 12, t1 = g1 - 12 * e1;
            float* ob0 = outv + (size_t)e0 * TD_ + t0 * 64;
            float* ob1 = outv + (size_t)e1 * TD_ + t1 * 64;
#pragma unroll
            for (int nt = 0; nt < 8; nt++) {
                int c = nt * 8 + col0;
                float bz0 = biasSh[c], bz1 = biasSh[c + 1];
                *(float2*)(ob0 + c) = make_float2(vac[u][nt][0] + bz0, vac[u][nt][1] + bz1);
                *(float2*)(ob1 + c) = make_float2(vac[u][nt][2] + bz0, vac[u][nt][3] + bz1);
            }
        }
        __syncwarp();
    }
}

// ---------------- softmax: one block/segment, 256 thr, exp cached, unroll-4 MLP ----------------
#define SMAX_SMEM (SMAX_CAP * TD_ * 4)   // 98,304 B
__global__ void __launch_bounds__(256)
k_softmax(float* __restrict__ v) {
    extern __shared__ float buf[];
    int seg = blockIdx.x;
    int beg = g_off[seg], end = g_off[seg + 1];
    int n = end - beg;
    if (n <= 0) return;
    int tid = threadIdx.x;
    int c0 = tid, c1 = tid + 256, c2 = tid + 512;
    if (n <= SMAX_CAP) {
        float s0 = 0.f, s1 = 0.f, s2 = 0.f;
        int i = 0;
        for (; i + 4 <= n; i += 4) {
#pragma unroll
            for (int q = 0; q < 4; q++) {
                const float* vp = v + (size_t)g_csr_s[beg + i + q] * TD_;
                float e0 = __expf(vp[c0]), e1 = __expf(vp[c1]), e2 = __expf(vp[c2]);
                buf[(i + q) * TD_ + c0] = e0;
                buf[(i + q) * TD_ + c1] = e1;
                buf[(i + q) * TD_ + c2] = e2;
                s0 += e0; s1 += e1; s2 += e2;
            }
        }
        for (; i < n; i++) {
            const float* vp = v + (size_t)g_csr_s[beg + i] * TD_;
            float e0 = __expf(vp[c0]), e1 = __expf(vp[c1]), e2 = __expf(vp[c2]);
            buf[i * TD_ + c0] = e0; buf[i * TD_ + c1] = e1; buf[i * TD_ + c2] = e2;
            s0 += e0; s1 += e1; s2 += e2;
        }
        float r0 = 1.f / (s0 + 1e-12f), r1 = 1.f / (s1 + 1e-12f), r2 = 1.f / (s2 + 1e-12f);
        for (int j = 0; j < n; j++) {
            float* vp = v + (size_t)g_csr_s[beg + j] * TD_;
            vp[c0] = buf[j * TD_ + c0] * r0;
            vp[c1] = buf[j * TD_ + c1] * r1;
            vp[c2] = buf[j * TD_ + c2] * r2;
        }
    } else {
        float s0 = 0.f, s1 = 0.f, s2 = 0.f;
        for (int i = beg; i < end; i++) {
            const float* vp = v + (size_t)g_csr_s[i] * TD_;
            s0 += __expf(vp[c0]); s1 += __expf(vp[c1]); s2 += __expf(vp[c2]);
        }
        float r0 = 1.f / (s0 + 1e-12f), r1 = 1.f / (s1 + 1e-12f), r2 = 1.f / (s2 + 1e-12f);
        for (int i = beg; i < end; i++) {
            float* vp = v + (size_t)g_csr_s[i] * TD_;
            vp[c0] = __expf(vp[c0]) * r0;
            vp[c1] = __expf(vp[c1]) * r1;
            vp[c2] = __expf(vp[c2]) * r2;
        }
    }
}

// ---------------- per-receiver aggregation + x update (unroll-4 MLP) ----------------
__global__ void __launch_bounds__(256)
k_aggregate(const float* __restrict__ x, const float* __restrict__ v,
            const int* __restrict__ bi, const int* __restrict__ si,
            float* __restrict__ outx) {
    int seg = blockIdx.x;
    int tid = threadIdx.x;
    int beg = g_off[(SEG_ + 1) + seg], end = g_off[(SEG_ + 1) + seg + 1];
    int c0 = tid, c1 = tid + 256, c2 = tid + 512;
    float a0 = 0.f, a1 = 0.f, a2 = 0.f;
    int i = beg;
    for (; i + 4 <= end; i += 4) {
        float p0 = 0.f, p1 = 0.f, p2 = 0.f;
#pragma unroll
        for (int q = 0; q < 4; q++) {
            int e = g_csr_r[i + q];
            int ns = bi[e] * N_ + si[e];
            const float* vp = v + (size_t)e * TD_;
            const float* xs = x + (size_t)ns * TD_;
            float v0 = vp[c0], v1 = vp[c1], v2 = vp[c2];
            float x0 = xs[c0], x1 = xs[c1], x2 = xs[c2];
            p0 = fmaf(v0, x0, p0); p1 = fmaf(v1, x1, p1); p2 = fmaf(v2, x2, p2);
        }
        a0 += p0; a1 += p1; a2 += p2;
    }
    for (; i < end; i++) {
        int e = g_csr_r[i];
        int ns = bi[e] * N_ + si[e];
        const float* vp = v + (size_t)e * TD_;
        const float* xs = x + (size_t)ns * TD_;
        a0 = fmaf(vp[c0], xs[c0], a0);
        a1 = fmaf(vp[c1], xs[c1], a1);
        a2 = fmaf(vp[c2], xs[c2], a2);
    }
    const float* xr = x + (size_t)seg * TD_;
    float* o = outx + (size_t)seg * TD_;
    o[c0] = xr[c0] + 0.1f * (a0 - xr[c0]);
    o[c1] = xr[c1] + 0.1f * (a1 - xr[c1]);
    o[c2] = xr[c2] + 0.1f * (a2 - xr[c2]);
}

// ---------------- launch: forked graph (CSR chain overlaps nodeproj+edge) ----------------
extern "C" void kernel_launch(void* const* d_in, const int* in_sizes, int n_in,
                              void* d_out, int out_size) {
    const float* x   = (const float*)d_in[0];
    const int*   bi  = (const int*)d_in[1];
    const int*   si  = (const int*)d_in[2];
    const int*   ri  = (const int*)d_in[3];
    const float* A1w = (const float*)d_in[4];
    const float* A1b = (const float*)d_in[5];
    const float* A2w = (const float*)d_in[6];
    const float* A2b = (const float*)d_in[7];
    const float* A3w = (const float*)d_in[8];
    // d_in[9] = A3_b: cancels in z_ij - z_ji
    const float* A4w = (const float*)d_in[10];
    const float* A4b = (const float*)d_in[11];

    float* outx = (float*)d_out;
    float* outv = outx + (size_t)ROWS_ * D_;

    cudaFuncSetAttribute(k_nodeproj, cudaFuncAttributeMaxDynamicSharedMemorySize, NPM_SMEM);
    cudaFuncSetAttribute(k_edge_mma, cudaFuncAttributeMaxDynamicSharedMemorySize, EM_SMEM);
    cudaFuncSetAttribute(k_softmax,  cudaFuncAttributeMaxDynamicSharedMemorySize, SMAX_SMEM);

    // fork a side stream off the captured origin stream (standard capture pattern)
    cudaStream_t s2;
    cudaStreamCreate(&s2);
    cudaEvent_t eFork, eJoin;
    cudaEventCreateWithFlags(&eFork, cudaEventDisableTiming);
    cudaEventCreateWithFlags(&eJoin, cudaEventDisableTiming);

    cudaEventRecord(eFork, 0);
    cudaStreamWaitEvent(s2, eFork, 0);

    // branch B (side stream): CSR chain
    k_count<<<(E_ + 255) / 256, 256, 0, s2>>>(bi, si, ri);
    k_scan2<<<2, 1024, 0, s2>>>();

    // branch A (origin): compute chain — edge stays at submission index 3 for ncu
    k_nodeproj<<<ROWS_ / 128, 256, NPM_SMEM>>>(x, A1w, A1b, A2w, A2b);
    k_edge_mma<<<296, 256, EM_SMEM>>>(bi, si, ri, A3w, A4w, A4b, outv);

    k_scatter<<<(E_ + 255) / 256, 256, 0, s2>>>(bi, si, ri);
    cudaEventRecord(eJoin, s2);
    cudaStreamWaitEvent(0, eJoin, 0);

    // joined: softmax + aggregate
    k_softmax<<<SEG_, 256, SMAX_SMEM>>>(outv);
    k_aggregate<<<SEG_, 256>>>(x, outv, bi, si, outx);
}

// round 17
// speedup vs baseline: 1.2290x; 1.0556x over previous
#include <cuda_runtime.h>
#include <cuda_bf16.h>
#include <cstdint>

#define B_    4
#define N_    1000
#define T_    12
#define D_    64
#define HID_  128
#define EF_   64
#define E_    64000
#define SEG_  (B_*N_)       // 4000
#define ROWS_ (SEG_*T_)     // 48000
#define TD_   (T_*D_)       // 768
#define TH_   (T_*HID_)     // 1536
#define MROWS_ (E_*T_)      // 768000
#define TILE_M 256
#define NTILE_ (MROWS_/TILE_M)   // 3000

// ---------------- device scratch ----------------
__device__ float g_S1[ROWS_ * HID_];
__device__ float g_S2[ROWS_ * HID_];
__device__ int   g_cnt[2 * SEG_];      // loader-zeroed; k_scan2 re-zeros after use
__device__ int   g_off[2 * (SEG_ + 1)];
__device__ int   g_cur[2 * SEG_];
__device__ int   g_csr_s[E_];
__device__ int   g_csr_r[E_];

// ---------------- mma.sync bf16 (sm_80+ legacy tensor path) ----------------
__device__ __forceinline__ void mma_bf16(float& d0, float& d1, float& d2, float& d3,
                                         uint32_t a0, uint32_t a1, uint32_t a2, uint32_t a3,
                                         uint32_t b0, uint32_t b1) {
    asm("mma.sync.aligned.m16n8k16.row.col.f32.bf16.bf16.f32 "
        "{%0,%1,%2,%3},{%4,%5,%6,%7},{%8,%9},{%0,%1,%2,%3};"
        : "+f"(d0), "+f"(d1), "+f"(d2), "+f"(d3)
        : "r"(a0), "r"(a1), "r"(a2), "r"(a3), "r"(b0), "r"(b1));
}

__device__ __forceinline__ void bf16_split2(float x, float y, uint32_t& hi, uint32_t& lo) {
    __nv_bfloat162 h2 = __float22bfloat162_rn(make_float2(x, y));
    hi = *(uint32_t*)&h2;
    float2 hf = __bfloat1622float2(h2);
    __nv_bfloat162 l2 = __float22bfloat162_rn(make_float2(x - hf.x, y - hf.y));
    lo = *(uint32_t*)&l2;
}

// ---------------- CSR build (parallel; zero folded into scan) ----------------
__global__ void k_count(const int* __restrict__ bi, const int* __restrict__ si,
                        const int* __restrict__ ri) {
    int e = blockIdx.x * blockDim.x + threadIdx.x;
    if (e >= E_) return;
    int b = bi[e];
    atomicAdd(&g_cnt[b * N_ + si[e]], 1);
    atomicAdd(&g_cnt[SEG_ + b * N_ + ri[e]], 1);
}

__global__ void k_scan2() {
    int which = blockIdx.x;
    int* cnt = g_cnt + which * SEG_;
    int* off = g_off + which * (SEG_ + 1);
    int* cur = g_cur + which * SEG_;
    __shared__ int part[1024];
    int tid = threadIdx.x;
    int l[4]; int s = 0;
#pragma unroll
    for (int j = 0; j < 4; j++) {
        int idx = tid * 4 + j;
        l[j] = (idx < SEG_) ? cnt[idx] : 0;
        if (idx < SEG_) cnt[idx] = 0;    // restore invariant for next graph replay
        s += l[j];
    }
    part[tid] = s;
    __syncthreads();
    for (int o = 1; o < 1024; o <<= 1) {
        int v = part[tid];
        int a = (tid >= o) ? part[tid - o] : 0;
        __syncthreads();
        part[tid] = v + a;
        __syncthreads();
    }
    int run = (tid > 0) ? part[tid - 1] : 0;
#pragma unroll
    for (int j = 0; j < 4; j++) {
        int idx = tid * 4 + j;
        if (idx < SEG_) { off[idx] = run; cur[idx] = run; run += l[j]; }
    }
    if (tid == 1023) off[SEG_] = part[1023];
}

__global__ void k_scatter(const int* __restrict__ bi, const int* __restrict__ si,
                          const int* __restrict__ ri) {
    int e = blockIdx.x * blockDim.x + threadIdx.x;
    if (e >= E_) return;
    int b = bi[e];
    int ps = atomicAdd(&g_cur[b * N_ + si[e]], 1);
    g_csr_s[ps] = e;
    int pr = atomicAdd(&g_cur[SEG_ + b * N_ + ri[e]], 1);
    g_csr_r[pr] = e;
}

// ---------------- node projection via mma (S1 = x@A1 + b12, S2 = x@A2) ----------------
#define NPM_B1H 0
#define NPM_B1L 16384
#define NPM_B2H 32768
#define NPM_B2L 49152
#define NPM_BIAS 65536
#define NPM_A   66048
#define NPM_SMEM (NPM_A + 8*4096)   // 98,816 B

__global__ void __launch_bounds__(256)
k_nodeproj(const float* __restrict__ x,
           const float* __restrict__ A1w, const float* __restrict__ A1b,
           const float* __restrict__ A2w, const float* __restrict__ A2b) {
    extern __shared__ char smem[];
    int tid = threadIdx.x;
    int w = tid >> 5;
    int l = tid & 31;

    for (int idx = tid; idx < 4096; idx += 256) {
        int lane = idx & 31, reg = (idx >> 5) & 1, nt = (idx >> 6) & 15, s = idx >> 10;
        int k = s * 16 + reg * 8 + 2 * (lane & 3);
        int n = nt * 8 + (lane >> 2);
        uint32_t hi, lo;
        bf16_split2(A1w[k * 128 + n], A1w[(k + 1) * 128 + n], hi, lo);
        *(uint32_t*)(smem + NPM_B1H + idx * 4) = hi;
        *(uint32_t*)(smem + NPM_B1L + idx * 4) = lo;
        bf16_split2(A2w[k * 128 + n], A2w[(k + 1) * 128 + n], hi, lo);
        *(uint32_t*)(smem + NPM_B2H + idx * 4) = hi;
        *(uint32_t*)(smem + NPM_B2L + idx * 4) = lo;
    }
    if (tid < 128) *(float*)(smem + NPM_BIAS + tid * 4) = A1b[tid] + A2b[tid];
    __syncthreads();

    char* Ah = smem + NPM_A + w * 4096;
    char* Al = Ah + 2048;
    const float* biasSh = (const float*)(smem + NPM_BIAS);

    int rowBase = blockIdx.x * 128 + w * 16;
    {
        int s = l >> 3;
        int khi = (l >> 2) & 1;
        int lf_lo = l & 3;
#pragma unroll 4
        for (int j = 0; j < 16; j++) {
            float2 xv = *(const float2*)(x + (size_t)(rowBase + j) * 64 + 2 * l);
            uint32_t hi, lo;
            bf16_split2(xv.x, xv.y, hi, lo);
            int reg = (j >> 3) + 2 * khi;
            int lane_f = (j & 7) * 4 + lf_lo;
            uint32_t word = (uint32_t)((s * 4 + reg) * 32 + (lane_f ^ (4 * s)));
            *(uint32_t*)(Ah + word * 4) = hi;
            *(uint32_t*)(Al + word * 4) = lo;
        }
    }
    __syncwarp();

    int lr0 = l >> 2;
    int col0 = 2 * (l & 3);

#pragma unroll
    for (int m = 0; m < 2; m++) {
        const char* BH = smem + (m == 0 ? NPM_B1H : NPM_B2H);
        const char* BL = smem + (m == 0 ? NPM_B1L : NPM_B2L);
        float acc[16][4];
#pragma unroll
        for (int nt = 0; nt < 16; nt++)
#pragma unroll
            for (int r = 0; r < 4; r++) acc[nt][r] = 0.f;
#pragma unroll
        for (int s = 0; s < 4; s++) {
            int lsw = l ^ (4 * s);
            uint32_t ah[4], al[4];
#pragma unroll
            for (int r = 0; r < 4; r++) {
                ah[r] = *(const uint32_t*)(Ah + ((s * 4 + r) * 32 + lsw) * 4);
                al[r] = *(const uint32_t*)(Al + ((s * 4 + r) * 32 + lsw) * 4);
            }
#pragma unroll
            for (int nt = 0; nt < 16; nt++) {
                uint32_t boff = (uint32_t)((((s * 16 + nt) * 2) * 32 + l) * 4);
                uint32_t bh0 = *(const uint32_t*)(BH + boff);
                uint32_t bh1 = *(const uint32_t*)(BH + boff + 128);
                uint32_t bl0 = *(const uint32_t*)(BL + boff);
                uint32_t bl1 = *(const uint32_t*)(BL + boff + 128);
                mma_bf16(acc[nt][0], acc[nt][1], acc[nt][2], acc[nt][3],
                         ah[0], ah[1], ah[2], ah[3], bh0, bh1);
                mma_bf16(acc[nt][0], acc[nt][1], acc[nt][2], acc[nt][3],
                         al[0], al[1], al[2], al[3], bh0, bh1);
                mma_bf16(acc[nt][0], acc[nt][1], acc[nt][2], acc[nt][3],
                         ah[0], ah[1], ah[2], ah[3], bl0, bl1);
            }
        }
        float* out = (m == 0) ? g_S1 : g_S2;
        float* ob0 = out + (size_t)(rowBase + lr0) * 128;
        float* ob1 = out + (size_t)(rowBase + lr0 + 8) * 128;
#pragma unroll
        for (int nt = 0; nt < 16; nt++) {
            int c = nt * 8 + col0;
            float bz0 = (m == 0) ? biasSh[c] : 0.f;
            float bz1 = (m == 0) ? biasSh[c + 1] : 0.f;
            *(float2*)(ob0 + c) = make_float2(acc[nt][0] + bz0, acc[nt][1] + bz1);
            *(float2*)(ob1 + c) = make_float2(acc[nt][2] + bz0, acc[nt][3] + bz1);
        }
    }
}

// ---------------- tensor-core edge kernel: 8 warps x 32 rows, K-split GEMM1 (R15/R16 proven) ----------------
#define SM_B1H  0
#define SM_B1L  16384
#define SM_B2H  32768
#define SM_B2L  40960
#define SM_BIAS 49152
#define SM_A1   49408
#define EM_SMEM (SM_A1 + 8*8192)             // 114,944 B

__global__ void __launch_bounds__(256, 2)
k_edge_mma(const int* __restrict__ bi, const int* __restrict__ si,
           const int* __restrict__ ri,
           const float* __restrict__ A3w, const float* __restrict__ A4w,
           const float* __restrict__ A4b, float* __restrict__ outv) {
    extern __shared__ char smem[];
    int tid = threadIdx.x;
    int w = tid >> 5;
    int l = tid & 31;

    for (int idx = tid; idx < 4096; idx += 256) {
        int lane = idx & 31, reg = (idx >> 5) & 1, nt = (idx >> 6) & 7, s = idx >> 9;
        int k = s * 16 + reg * 8 + 2 * (lane & 3);
        int n = nt * 8 + (lane >> 2);
        uint32_t hi, lo;
        bf16_split2(A3w[k * 64 + n], A3w[(k + 1) * 64 + n], hi, lo);
        *(uint32_t*)(smem + SM_B1H + idx * 4) = hi;
        *(uint32_t*)(smem + SM_B1L + idx * 4) = lo;
    }
    for (int idx = tid; idx < 2048; idx += 256) {
        int lane = idx & 31, reg = (idx >> 5) & 1, nt = (idx >> 6) & 7, s = idx >> 9;
        int k = s * 16 + reg * 8 + 2 * (lane & 3);
        int n = nt * 8 + (lane >> 2);
        uint32_t hi, lo;
        bf16_split2(A4w[k * 64 + n], A4w[(k + 1) * 64 + n], hi, lo);
        *(uint32_t*)(smem + SM_B2H + idx * 4) = hi;
        *(uint32_t*)(smem + SM_B2L + idx * 4) = lo;
    }
    if (tid < 64) *(float*)(smem + SM_BIAS + tid * 4) = A4b[tid];
    __syncthreads();

    char* Abase = smem + SM_A1 + w * 8192;   // [u: 4 KB][hi 2 KB | lo 2 KB]
    const float* biasSh = (const float*)(smem + SM_BIAS);

    int rp = l >> 4;
    int cq = l & 15;
    int bsl  = cq >> 2;
    int bkhi = (l >> 1) & 1;
    int bpr  = 2 * (l & 1);
    int lr0 = l >> 2;
    int col0 = 2 * (l & 3);

    for (int tile = blockIdx.x; tile < NTILE_; tile += gridDim.x) {
        float acc[2][8][4];
#pragma unroll
        for (int u = 0; u < 2; u++)
#pragma unroll
            for (int nt = 0; nt < 8; nt++)
#pragma unroll
                for (int r = 0; r < 4; r++) acc[u][nt][r] = 0.f;

#pragma unroll
        for (int h = 0; h < 2; h++) {
            __syncwarp();
#pragma unroll
            for (int u = 0; u < 2; u++) {
                char* Ah = Abase + u * 4096;
                char* Al = Ah + 2048;
#pragma unroll 2
                for (int j = 0; j < 8; j++) {
                    int r_sub = 2 * j + rp;
                    int g = tile * TILE_M + w * 32 + u * 16 + r_sub;
                    int e = g / 12, tt = g - e * 12;
                    int bb = bi[e];
                    int ns = bb * N_ + si[e], nr = bb * N_ + ri[e];
                    size_t o = (size_t)tt * 128 + 64 * h + 4 * cq;
                    float4 a  = *(const float4*)(g_S1 + (size_t)ns * TH_ + o);
                    float4 d  = *(const float4*)(g_S2 + (size_t)ns * TH_ + o);
                    float4 c  = *(const float4*)(g_S1 + (size_t)nr * TH_ + o);
                    float4 b4 = *(const float4*)(g_S2 + (size_t)nr * TH_ + o);
                    float h0 = fmaxf(a.x + b4.x, 0.f) - fmaxf(c.x + d.x, 0.f);
                    float h1 = fmaxf(a.y + b4.y, 0.f) - fmaxf(c.y + d.y, 0.f);
                    float h2 = fmaxf(a.z + b4.z, 0.f) - fmaxf(c.z + d.z, 0.f);
                    float h3 = fmaxf(a.w + b4.w, 0.f) - fmaxf(c.w + d.w, 0.f);
                    uint32_t hiA, loA, hiB, loB;
                    bf16_split2(h0, h1, hiA, loA);
                    bf16_split2(h2, h3, hiB, loB);
                    int reg = (r_sub >> 3) + 2 * bkhi;
                    int lane_f = (r_sub & 7) * 4 + bpr;
                    uint32_t word = (uint32_t)((bsl * 4 + reg) * 32 + (lane_f ^ (4 * bsl)));
                    *(uint2*)(Ah + word * 4) = make_uint2(hiA, hiB);
                    *(uint2*)(Al + word * 4) = make_uint2(loA, loB);
                }
            }
            __syncwarp();

#pragma unroll
            for (int sl = 0; sl < 4; sl++) {
                int lsw = l ^ (4 * sl);
                uint32_t ah[2][4], al[2][4];
#pragma unroll
                for (int u = 0; u < 2; u++)
#pragma unroll
                    for (int r = 0; r < 4; r++) {
                        ah[u][r] = *(const uint32_t*)(Abase + u * 4096 + ((sl * 4 + r) * 32 + lsw) * 4);
                        al[u][r] = *(const uint32_t*)(Abase + u * 4096 + 2048 + ((sl * 4 + r) * 32 + lsw) * 4);
                    }
                int s = 4 * h + sl;
#pragma unroll
                for (int nt = 0; nt < 8; nt++) {
                    uint32_t boff = (uint32_t)((((s * 8 + nt) * 2) * 32 + l) * 4);
                    uint32_t bh0 = *(const uint32_t*)(smem + SM_B1H + boff);
                    uint32_t bh1 = *(const uint32_t*)(smem + SM_B1H + boff + 128);
                    uint32_t bl0 = *(const uint32_t*)(smem + SM_B1L + boff);
                    uint32_t bl1 = *(const uint32_t*)(smem + SM_B1L + boff + 128);
#pragma unroll
                    for (int u = 0; u < 2; u++) {
                        mma_bf16(acc[u][nt][0], acc[u][nt][1], acc[u][nt][2], acc[u][nt][3],
                                 ah[u][0], ah[u][1], ah[u][2], ah[u][3], bh0, bh1);
                        mma_bf16(acc[u][nt][0], acc[u][nt][1], acc[u][nt][2], acc[u][nt][3],
                                 al[u][0], al[u][1], al[u][2], al[u][3], bh0, bh1);
                        mma_bf16(acc[u][nt][0], acc[u][nt][1], acc[u][nt][2], acc[u][nt][3],
                                 ah[u][0], ah[u][1], ah[u][2], ah[u][3], bl0, bl1);
                    }
                }
            }
        }
        __syncwarp();

#pragma unroll
        for (int u = 0; u < 2; u++) {
            char* A2h = Abase + u * 4096;
            char* A2l = A2h + 2048;
#pragma unroll
            for (int nt = 0; nt < 8; nt++) {
                float x0 = fmaxf(acc[u][nt][0], 0.f), x1 = fmaxf(acc[u][nt][1], 0.f);
                float x2 = fmaxf(acc[u][nt][2], 0.f), x3 = fmaxf(acc[u][nt][3], 0.f);
                uint32_t hi0, lo0, hi1, lo1;
                bf16_split2(x0, x1, hi0, lo0);
                bf16_split2(x2, x3, hi1, lo1);
                int s2 = nt >> 1, khi = nt & 1;
                int lsw = l ^ (4 * s2);
                uint32_t o0 = (uint32_t)(((s2 * 4 + 2 * khi + 0) * 32 + lsw) * 4);
                uint32_t o1 = (uint32_t)(((s2 * 4 + 2 * khi + 1) * 32 + lsw) * 4);
                *(uint32_t*)(A2h + o0) = hi0;
                *(uint32_t*)(A2h + o1) = hi1;
                *(uint32_t*)(A2l + o0) = lo0;
                *(uint32_t*)(A2l + o1) = lo1;
            }
        }
        __syncwarp();

        float vac[2][8][4];
#pragma unroll
        for (int u = 0; u < 2; u++)
#pragma unroll
            for (int nt = 0; nt < 8; nt++)
#pragma unroll
                for (int r = 0; r < 4; r++) vac[u][nt][r] = 0.f;
#pragma unroll
        for (int s = 0; s < 4; s++) {
            int lsw = l ^ (4 * s);
            uint32_t ah[2][4], al[2][4];
#pragma unroll
            for (int u = 0; u < 2; u++)
#pragma unroll
                for (int r = 0; r < 4; r++) {
                    ah[u][r] = *(const uint32_t*)(Abase + u * 4096 + ((s * 4 + r) * 32 + lsw) * 4);
                    al[u][r] = *(const uint32_t*)(Abase + u * 4096 + 2048 + ((s * 4 + r) * 32 + lsw) * 4);
                }
#pragma unroll
            for (int nt = 0; nt < 8; nt++) {
                uint32_t boff = (uint32_t)((((s * 8 + nt) * 2) * 32 + l) * 4);
                uint32_t bh0 = *(const uint32_t*)(smem + SM_B2H + boff);
                uint32_t bh1 = *(const uint32_t*)(smem + SM_B2H + boff + 128);
                uint32_t bl0 = *(const uint32_t*)(smem + SM_B2L + boff);
                uint32_t bl1 = *(const uint32_t*)(smem + SM_B2L + boff + 128);
#pragma unroll
                for (int u = 0; u < 2; u++) {
                    mma_bf16(vac[u][nt][0], vac[u][nt][1], vac[u][nt][2], vac[u][nt][3],
                             ah[u][0], ah[u][1], ah[u][2], ah[u][3], bh0, bh1);
                    mma_bf16(vac[u][nt][0], vac[u][nt][1], vac[u][nt][2], vac[u][nt][3],
                             al[u][0], al[u][1], al[u][2], al[u][3], bh0, bh1);
                    mma_bf16(vac[u][nt][0], vac[u][nt][1], vac[u][nt][2], vac[u][nt][3],
                             ah[u][0], ah[u][1], ah[u][2], ah[u][3], bl0, bl1);
                }
            }
        }

#pragma unroll
        for (int u = 0; u < 2; u++) {
            int g0 = tile * TILE_M + w * 32 + u * 16 + lr0;
            int e0 = g0 / 12, t0 = g0 - 12 * e0;
            int g1 = g0 + 8;
            int e1 = g1 / 12, t1 = g1 - 12 * e1;
            float* ob0 = outv + (size_t)e0 * TD_ + t0 * 64;
            float* ob1 = outv + (size_t)e1 * TD_ + t1 * 64;
#pragma unroll
            for (int nt = 0; nt < 8; nt++) {
                int c = nt * 8 + col0;
                float bz0 = biasSh[c], bz1 = biasSh[c + 1];
                *(float2*)(ob0 + c) = make_float2(vac[u][nt][0] + bz0, vac[u][nt][1] + bz1);
                *(float2*)(ob1 + c) = make_float2(vac[u][nt][2] + bz0, vac[u][nt][3] + bz1);
            }
        }
        __syncwarp();
    }
}

// ---------------- softmax: 2-pass, NO smem (pass-2 reads are L2-hot), unroll-4 ----------------
__global__ void __launch_bounds__(256)
k_softmax(float* __restrict__ v) {
    int seg = blockIdx.x;
    int beg = g_off[seg], end = g_off[seg + 1];
    if (beg == end) return;
    int tid = threadIdx.x;
    int c0 = tid, c1 = tid + 256, c2 = tid + 512;
    float s0 = 0.f, s1 = 0.f, s2 = 0.f;
    int i = beg;
    for (; i + 4 <= end; i += 4) {
        float p0 = 0.f, p1 = 0.f, p2 = 0.f;
#pragma unroll
        for (int q = 0; q < 4; q++) {
            const float* vp = v + (size_t)g_csr_s[i + q] * TD_;
            p0 += __expf(vp[c0]); p1 += __expf(vp[c1]); p2 += __expf(vp[c2]);
        }
        s0 += p0; s1 += p1; s2 += p2;
    }
    for (; i < end; i++) {
        const float* vp = v + (size_t)g_csr_s[i] * TD_;
        s0 += __expf(vp[c0]); s1 += __expf(vp[c1]); s2 += __expf(vp[c2]);
    }
    float r0 = 1.f / (s0 + 1e-12f), r1 = 1.f / (s1 + 1e-12f), r2 = 1.f / (s2 + 1e-12f);
    i = beg;
    for (; i + 2 <= end; i += 2) {
        float* vpA = v + (size_t)g_csr_s[i] * TD_;
        float* vpB = v + (size_t)g_csr_s[i + 1] * TD_;
        float a0 = vpA[c0], a1 = vpA[c1], a2 = vpA[c2];
        float b0 = vpB[c0], b1 = vpB[c1], b2 = vpB[c2];
        vpA[c0] = __expf(a0) * r0; vpA[c1] = __expf(a1) * r1; vpA[c2] = __expf(a2) * r2;
        vpB[c0] = __expf(b0) * r0; vpB[c1] = __expf(b1) * r1; vpB[c2] = __expf(b2) * r2;
    }
    if (i < end) {
        float* vp = v + (size_t)g_csr_s[i] * TD_;
        vp[c0] = __expf(vp[c0]) * r0;
        vp[c1] = __expf(vp[c1]) * r1;
        vp[c2] = __expf(vp[c2]) * r2;
    }
}

// ---------------- per-receiver aggregation + x update (unroll-4 MLP) ----------------
__global__ void __launch_bounds__(256)
k_aggregate(const float* __restrict__ x, const float* __restrict__ v,
            const int* __restrict__ bi, const int* __restrict__ si,
            float* __restrict__ outx) {
    int seg = blockIdx.x;
    int tid = threadIdx.x;
    int beg = g_off[(SEG_ + 1) + seg], end = g_off[(SEG_ + 1) + seg + 1];
    int c0 = tid, c1 = tid + 256, c2 = tid + 512;
    float a0 = 0.f, a1 = 0.f, a2 = 0.f;
    int i = beg;
    for (; i + 4 <= end; i += 4) {
        float p0 = 0.f, p1 = 0.f, p2 = 0.f;
#pragma unroll
        for (int q = 0; q < 4; q++) {
            int e = g_csr_r[i + q];
            int ns = bi[e] * N_ + si[e];
            const float* vp = v + (size_t)e * TD_;
            const float* xs = x + (size_t)ns * TD_;
            float v0 = vp[c0], v1 = vp[c1], v2 = vp[c2];
            float x0 = xs[c0], x1 = xs[c1], x2 = xs[c2];
            p0 = fmaf(v0, x0, p0); p1 = fmaf(v1, x1, p1); p2 = fmaf(v2, x2, p2);
        }
        a0 += p0; a1 += p1; a2 += p2;
    }
    for (; i < end; i++) {
        int e = g_csr_r[i];
        int ns = bi[e] * N_ + si[e];
        const float* vp = v + (size_t)e * TD_;
        const float* xs = x + (size_t)ns * TD_;
        a0 = fmaf(vp[c0], xs[c0], a0);
        a1 = fmaf(vp[c1], xs[c1], a1);
        a2 = fmaf(vp[c2], xs[c2], a2);
    }
    const float* xr = x + (size_t)seg * TD_;
    float* o = outx + (size_t)seg * TD_;
    o[c0] = xr[c0] + 0.1f * (a0 - xr[c0]);
    o[c1] = xr[c1] + 0.1f * (a1 - xr[c1]);
    o[c2] = xr[c2] + 0.1f * (a2 - xr[c2]);
}

// ---------------- launch: forked graph (CSR chain overlaps nodeproj+edge) ----------------
extern "C" void kernel_launch(void* const* d_in, const int* in_sizes, int n_in,
                              void* d_out, int out_size) {
    const float* x   = (const float*)d_in[0];
    const int*   bi  = (const int*)d_in[1];
    const int*   si  = (const int*)d_in[2];
    const int*   ri  = (const int*)d_in[3];
    const float* A1w = (const float*)d_in[4];
    const float* A1b = (const float*)d_in[5];
    const float* A2w = (const float*)d_in[6];
    const float* A2b = (const float*)d_in[7];
    const float* A3w = (const float*)d_in[8];
    // d_in[9] = A3_b: cancels in z_ij - z_ji
    const float* A4w = (const float*)d_in[10];
    const float* A4b = (const float*)d_in[11];

    float* outx = (float*)d_out;
    float* outv = outx + (size_t)ROWS_ * D_;

    cudaFuncSetAttribute(k_nodeproj, cudaFuncAttributeMaxDynamicSharedMemorySize, NPM_SMEM);
    cudaFuncSetAttribute(k_edge_mma, cudaFuncAttributeMaxDynamicSharedMemorySize, EM_SMEM);

    // fork a side stream off the captured origin stream (standard capture pattern)
    cudaStream_t s2;
    cudaStreamCreate(&s2);
    cudaEvent_t eFork, eJoin;
    cudaEventCreateWithFlags(&eFork, cudaEventDisableTiming);
    cudaEventCreateWithFlags(&eJoin, cudaEventDisableTiming);

    cudaEventRecord(eFork, 0);
    cudaStreamWaitEvent(s2, eFork, 0);

    // branch B (side stream): CSR chain
    k_count<<<(E_ + 255) / 256, 256, 0, s2>>>(bi, si, ri);
    k_scan2<<<2, 1024, 0, s2>>>();

    // branch A (origin): compute chain — edge stays at submission index 3 for ncu
    k_nodeproj<<<ROWS_ / 128, 256, NPM_SMEM>>>(x, A1w, A1b, A2w, A2b);
    k_edge_mma<<<296, 256, EM_SMEM>>>(bi, si, ri, A3w, A4w, A4b, outv);

    k_scatter<<<(E_ + 255) / 256, 256, 0, s2>>>(bi, si, ri);
    cudaEventRecord(eJoin, s2);
    cudaStreamWaitEvent(0, eJoin, 0);

    // joined: softmax + aggregate
    k_softmax<<<SEG_, 256>>>(outv);
    k_aggregate<<<SEG_, 256>>>(x, outv, bi, si, outx);
}